// round 1
// baseline (speedup 1.0000x reference)
#include <cuda_runtime.h>
#include <math.h>

#define DIV_UP(a,b) (((a)+(b)-1)/(b))

// Problem constants (fixed by setup_inputs)
constexpr int cB   = 16;
constexpr int cT   = 24;
constexpr int cN   = 500;
constexpr int cF   = 2;
constexpr int cH   = 64;
constexpr int cD   = 8;
constexpr int cTGN = 32;
constexpr int cHYP = 16;
constexpr int cLEN = 24;
constexpr int cB4  = cB * 4;

constexpr float kAL = 0.05f, kBE = 0.95f, kGA = 0.95f, kTAU = 2.0f;

constexpr int LDS_ = 3 * cH;          // 192  (gcn_single chain width, H input)
constexpr int LDZ  = 3 * (cF + cH);   // 198  (gcn_rnn chain width)
constexpr int LDT  = 3 * cF;          // 6    (tgn chain width)

// ---------------- scratch (static device globals; no allocations) ----------
__device__ float g_hidden[cB * cN * cH];
__device__ float g_chainS[cB * cN * LDS_];
__device__ float g_gs[cB * cN * cHYP];
__device__ float g_gt[cB * cN * cHYP];
__device__ float g_ns[cB * cN * cHYP];
__device__ float g_nt[cB * cN * cHYP];
__device__ float g_adp[(size_t)cB * cN * cN];
__device__ float g_chainZ[cB * cN * LDZ];
__device__ float g_z[cB * cN * cH];
__device__ float g_r[cB * cN * cH];
__device__ float g_Atgn[(size_t)cB4 * cN * cN];
__device__ float g_q[cB * cN * cD];
__device__ float g_k[cB4 * cN * cD];
__device__ float g_chainT[cB4 * cN * LDT];
__device__ float g_tgnh[cB4 * cN * cTGN];
__device__ float g_tar2[cB * cN * cTGN];
__device__ float g_gat[cB * cN * cF];

// ---------------- kernels --------------------------------------------------

__global__ void k_zero(float* p, int ntot) {
    int i = blockIdx.x * blockDim.x + threadIdx.x;
    if (i < ntot) p[i] = 0.f;
}

// Fused graph conv: out slice = AL*x + sum_v h[v,c]*(c1*A1[b,v,w] + c2*A2[b,v,w])
// x is always slice 0 of the chain buffer. A1 may be null (then c1 ignored).
__global__ void k_gconv(float* __restrict__ buf, int ldc, int C,
                        int sIn, int sOut,
                        const float* __restrict__ A1, size_t A1bs, float c1,
                        const float* __restrict__ A2, size_t A2bs, float c2,
                        int n)
{
    int b  = blockIdx.y;
    int w0 = blockIdx.x * 32;
    int wi = threadIdx.x & 31;
    int cg = threadIdx.x >> 5;              // 0..7

    __shared__ float A1s[32][33];
    __shared__ float A2s[32][33];
    __shared__ float hs[32][68];

    float acc[9];
#pragma unroll
    for (int j = 0; j < 9; j++) acc[j] = 0.f;

    const float* A1b = A1 ? A1 + (size_t)b * A1bs : nullptr;
    const float* A2b = A2 + (size_t)b * A2bs;
    const float* hin = buf + (size_t)b * n * ldc + sIn * C;

    for (int v0 = 0; v0 < n; v0 += 32) {
        for (int l = threadIdx.x; l < 32 * 32; l += 256) {
            int vi = l >> 5, wj = l & 31;
            int v = v0 + vi, w = w0 + wj;
            bool ok = (v < n) && (w < n);
            A2s[vi][wj] = ok ? A2b[(size_t)v * n + w] : 0.f;
            A1s[vi][wj] = (A1b && ok) ? A1b[(size_t)v * n + w] : 0.f;
        }
        for (int l = threadIdx.x; l < 32 * C; l += 256) {
            int vi = l / C, c = l - vi * C;
            int v = v0 + vi;
            hs[vi][c] = (v < n) ? hin[(size_t)v * ldc + c] : 0.f;
        }
        __syncthreads();

#pragma unroll 4
        for (int v = 0; v < 32; v++) {
            float coef = c2 * A2s[v][wi] + c1 * A1s[v][wi];
#pragma unroll
            for (int j = 0; j < 9; j++) {
                int c = cg + j * 8;
                if (c < C) acc[j] = fmaf(coef, hs[v][c], acc[j]);
            }
        }
        __syncthreads();
    }

    int w = w0 + wi;
    if (w < n) {
        float* outp = buf + ((size_t)b * n + w) * ldc;
#pragma unroll
        for (int j = 0; j < 9; j++) {
            int c = cg + j * 8;
            if (c < C) outp[sOut * C + c] = kAL * outp[c] + acc[j];
        }
    }
}

// Generic small matmul + epilogue.
// modes: 0 plain | 1 sigmoid | 2 relu | 3 tanh(TAU*v*gate) | 4 GRU hidden update
//        5 plain with transposed store out[b,m,n]
__global__ void k_matmul(const float* __restrict__ in, size_t inBs, int K,
                         const float* __restrict__ in2, int K2,
                         const float* __restrict__ W, const float* __restrict__ bias, int M,
                         float* __restrict__ out, int mode,
                         const float* __restrict__ gate,
                         const float* __restrict__ zb, float* __restrict__ hid,
                         int Bn, int n)
{
    int gid = blockIdx.x * blockDim.x + threadIdx.x;
    int total = Bn * n * M;
    if (gid >= total) return;
    int m   = gid % M;
    int row = gid / M;
    int nn  = row % n;
    int b   = row / n;

    const float* inr = in + (size_t)b * inBs + (size_t)nn * K;
    float acc = bias[m];
    for (int k = 0; k < K; k++) acc = fmaf(inr[k], W[k * M + m], acc);
    if (in2) {
        const float* in2r = in2 + ((size_t)b * n + nn) * K2;
        for (int k = 0; k < K2; k++) acc = fmaf(in2r[k], W[(K + k) * M + m], acc);
    }

    size_t oi = ((size_t)b * n + nn) * M + m;
    if (mode == 0)      out[oi] = acc;
    else if (mode == 1) out[oi] = 1.f / (1.f + expf(-acc));
    else if (mode == 2) out[oi] = fmaxf(acc, 0.f);
    else if (mode == 3) out[oi] = tanhf(kTAU * acc * gate[oi]);
    else if (mode == 4) {
        float h = hid[oi]; float zz = zb[oi];
        hid[oi] = zz * h + (1.f - zz) * tanhf(acc);
    } else { // mode 5: transposed (B, M, n)
        out[(size_t)b * M * n + (size_t)m * n + nn] = acc;
    }
}

// adp[b,i,:] = rownorm( relu(tanh(TAU*(ns_i . nt_m - nt_i . ns_m))) + I )
__global__ void k_adp(const float* __restrict__ ns, const float* __restrict__ nt,
                      float* __restrict__ adp, int n)
{
    int b = blockIdx.y, i = blockIdx.x;
    int tid = threadIdx.x;
    __shared__ float nsr[16], ntr[16];
    __shared__ float rowbuf[512];
    __shared__ float red[128];

    if (tid < 16) {
        nsr[tid] = ns[((size_t)b * n + i) * 16 + tid];
        ntr[tid] = nt[((size_t)b * n + i) * 16 + tid];
    }
    __syncthreads();

    float lsum = 0.f;
    for (int m = tid; m < n; m += 128) {
        const float* nsm = ns + ((size_t)b * n + m) * 16;
        const float* ntm = nt + ((size_t)b * n + m) * 16;
        float a = 0.f;
#pragma unroll
        for (int c = 0; c < 16; c++) a += nsr[c] * ntm[c] - ntr[c] * nsm[c];
        float v = tanhf(kTAU * a);
        v = fmaxf(v, 0.f);
        if (m == i) v += 1.f;
        rowbuf[m] = v;
        lsum += v;
    }
    red[tid] = lsum; __syncthreads();
    for (int s = 64; s > 0; s >>= 1) { if (tid < s) red[tid] += red[tid + s]; __syncthreads(); }
    float inv = 1.f / red[0];
    for (int m = tid; m < n; m += 128)
        adp[((size_t)b * n + i) * n + m] = rowbuf[m] * inv;
}

// scores + softmax + A_tgn = adj + attn, one (bt,i) row per block
__global__ void k_attn(const float* __restrict__ q, const float* __restrict__ kk,
                       const float* __restrict__ tw, const float* __restrict__ adj,
                       float* __restrict__ Atgn, int n)
{
    int bt = blockIdx.y, i = blockIdx.x;
    int b = bt >> 2;
    int tid = threadIdx.x;
    __shared__ float qd[8], twv[8];
    __shared__ float rowbuf[512];
    __shared__ float red[128];

    if (tid < 8) {
        qd[tid]  = q[((size_t)b * n + i) * 8 + tid];
        twv[tid] = tw[tid];
    }
    __syncthreads();

    float lmax = -1e30f;
    for (int j = tid; j < n; j += 128) {
        const float* kj = kk + ((size_t)bt * n + j) * 8;
        float s = 0.f;
#pragma unroll
        for (int d = 0; d < 8; d++) s += tanhf(qd[d] + kj[d]) * twv[d];
        rowbuf[j] = s;
        lmax = fmaxf(lmax, s);
    }
    red[tid] = lmax; __syncthreads();
    for (int s = 64; s > 0; s >>= 1) { if (tid < s) red[tid] = fmaxf(red[tid], red[tid + s]); __syncthreads(); }
    float gmax = red[0];
    __syncthreads();

    float lsum = 0.f;
    for (int j = tid; j < n; j += 128) {
        float e = expf(rowbuf[j] - gmax);
        rowbuf[j] = e; lsum += e;
    }
    red[tid] = lsum; __syncthreads();
    for (int s = 64; s > 0; s >>= 1) { if (tid < s) red[tid] += red[tid + s]; __syncthreads(); }
    float inv = 1.f / red[0];
    for (int j = tid; j < n; j += 128)
        Atgn[((size_t)bt * n + i) * n + j] = adj[(size_t)i * n + j] + rowbuf[j] * inv;
}

__global__ void k_pack_chainS(const float* __restrict__ hidden, float* __restrict__ chainS, int n)
{
    int i = blockIdx.x * blockDim.x + threadIdx.x;
    int total = cB * n * cH;
    if (i >= total) return;
    int c = i % cH;
    int row = i / cH;
    chainS[(size_t)row * LDS_ + c] = hidden[i];
}

__global__ void k_pack_comb(const float* __restrict__ cur, size_t curBs,
                            const float* __restrict__ hidden, const float* __restrict__ rmul,
                            float* __restrict__ chainZ, int n)
{
    int i = blockIdx.x * blockDim.x + threadIdx.x;
    int total = cB * n * (cF + cH);
    if (i >= total) return;
    int c = i % (cF + cH);
    int row = i / (cF + cH);
    int nn = row % n; int b = row / n;
    float v;
    if (c < cF) v = cur[(size_t)b * curBs + (size_t)nn * cF + c];
    else {
        v = hidden[(size_t)row * cH + (c - cF)];
        if (rmul) v *= rmul[(size_t)row * cH + (c - cF)];
    }
    chainZ[(size_t)row * LDZ + c] = v;
}

__global__ void k_pack_tgn(const float* __restrict__ X, float* __restrict__ chainT, int n)
{
    int i = blockIdx.x * blockDim.x + threadIdx.x;
    int total = cB4 * n * cF;
    if (i >= total) return;
    int f = i % cF;
    int row = i / cF;
    int nn = row % n; int bt = row / n;
    int b = bt >> 2, t = bt & 3;
    chainT[(size_t)row * LDT + f] =
        X[((((size_t)b * cT) + (cT - 4) + t) * n + nn) * cF + f];
}

__global__ void k_qk(const float* __restrict__ X,
                     const float* __restrict__ wqw, const float* __restrict__ wqb,
                     const float* __restrict__ wkw, const float* __restrict__ wkb,
                     float* __restrict__ q, float* __restrict__ kk, int n)
{
    int i = blockIdx.x * blockDim.x + threadIdx.x;
    int total = cB4 * n * cD;
    if (i >= total) return;
    int d = i % cD;
    int row = i / cD;
    int nn = row % n; int bt = row / n;
    int b = bt >> 2, t = bt & 3;
    const float* xr = X + ((((size_t)b * cT) + (cT - 4) + t) * n + nn) * cF;
    kk[i] = wkb[d] + xr[0] * wkw[d] + xr[1] * wkw[cD + d];
    if (t == 3)
        q[((size_t)b * n + nn) * cD + d] = wqb[d] + xr[0] * wqw[d] + xr[1] * wqw[cD + d];
}

__global__ void k_reduce_t(const float* __restrict__ tgnh, float* __restrict__ tar2, int n)
{
    int i = blockIdx.x * blockDim.x + threadIdx.x;
    int total = cB * n * cTGN;
    if (i >= total) return;
    int c = i % cTGN;
    int row = i / cTGN;
    int nn = row % n; int b = row / n;
    float s = 0.f;
#pragma unroll
    for (int t = 0; t < 4; t++)
        s += tgnh[((((size_t)b * 4) + t) * n + nn) * cTGN + c];
    tar2[i] = s;
}

// ---------------- host orchestration ---------------------------------------

struct Ptrs {
    float *hidden, *chainS, *gs, *gt, *ns, *nt, *adp, *chainZ, *zb, *rb;
    float *Atgn, *q, *k, *chainT, *tgnh, *tar2, *gat;
};

static void gru_step(const float* cur, size_t curBs, const float* adj,
                     const float* agg1_w, const float* agg1_b,
                     const float* agg2_w, const float* agg2_b,
                     const float* src_w, const float* src_b,
                     const float* tgt_w, const float* tgt_b,
                     const float* gz_w, const float* gz_b,
                     const float* gr_w, const float* gr_b,
                     const float* gc_w, const float* gc_b,
                     const Ptrs& P)
{
    const int n = cN;
    dim3 gg(DIV_UP(n, 32), cB);

    // shared gcn_single chain on hidden (feeds both gs and gt)
    k_pack_chainS<<<DIV_UP(cB * n * cH, 256), 256>>>(P.hidden, P.chainS, n);
    k_gconv<<<gg, 256>>>(P.chainS, LDS_, cH, 0, 1, nullptr, 0, 0.f, adj, 0, kGA, n);
    k_gconv<<<gg, 256>>>(P.chainS, LDS_, cH, 1, 2, nullptr, 0, 0.f, adj, 0, kGA, n);
    k_matmul<<<DIV_UP(cB * n * cHYP, 256), 256>>>(P.chainS, (size_t)n * LDS_, LDS_, nullptr, 0,
        agg1_w, agg1_b, cHYP, P.gs, 0, nullptr, nullptr, nullptr, cB, n);
    k_matmul<<<DIV_UP(cB * n * cHYP, 256), 256>>>(P.chainS, (size_t)n * LDS_, LDS_, nullptr, 0,
        agg2_w, agg2_b, cHYP, P.gt, 0, nullptr, nullptr, nullptr, cB, n);

    // ns / nt
    k_matmul<<<DIV_UP(cB * n * cHYP, 256), 256>>>(cur, curBs, cF, nullptr, 0,
        src_w, src_b, cHYP, P.ns, 3, P.gs, nullptr, nullptr, cB, n);
    k_matmul<<<DIV_UP(cB * n * cHYP, 256), 256>>>(cur, curBs, cF, nullptr, 0,
        tgt_w, tgt_b, cHYP, P.nt, 3, P.gt, nullptr, nullptr, cB, n);

    // adaptive adjacency
    k_adp<<<dim3(n, cB), 128>>>(P.ns, P.nt, P.adp, n);

    // shared gcn_rnn chain on [cur, hidden] (feeds both z and r)
    k_pack_comb<<<DIV_UP(cB * n * (cF + cH), 256), 256>>>(cur, curBs, P.hidden, nullptr, P.chainZ, n);
    k_gconv<<<gg, 256>>>(P.chainZ, LDZ, cF + cH, 0, 1, P.adp, (size_t)n * n, kBE, adj, 0, kGA, n);
    k_gconv<<<gg, 256>>>(P.chainZ, LDZ, cF + cH, 1, 2, P.adp, (size_t)n * n, kBE, adj, 0, kGA, n);
    k_matmul<<<DIV_UP(cB * n * cH, 256), 256>>>(P.chainZ, (size_t)n * LDZ, LDZ, nullptr, 0,
        gz_w, gz_b, cH, P.zb, 1, nullptr, nullptr, nullptr, cB, n);
    k_matmul<<<DIV_UP(cB * n * cH, 256), 256>>>(P.chainZ, (size_t)n * LDZ, LDZ, nullptr, 0,
        gr_w, gr_b, cH, P.rb, 1, nullptr, nullptr, nullptr, cB, n);

    // c chain on [cur, r*hidden], then fused hidden update
    k_pack_comb<<<DIV_UP(cB * n * (cF + cH), 256), 256>>>(cur, curBs, P.hidden, P.rb, P.chainZ, n);
    k_gconv<<<gg, 256>>>(P.chainZ, LDZ, cF + cH, 0, 1, P.adp, (size_t)n * n, kBE, adj, 0, kGA, n);
    k_gconv<<<gg, 256>>>(P.chainZ, LDZ, cF + cH, 1, 2, P.adp, (size_t)n * n, kBE, adj, 0, kGA, n);
    k_matmul<<<DIV_UP(cB * n * cH, 256), 256>>>(P.chainZ, (size_t)n * LDZ, LDZ, nullptr, 0,
        gc_w, gc_b, cH, P.hidden /*unused*/, 4, nullptr, P.zb, P.hidden, cB, n);
}

extern "C" void kernel_launch(void* const* d_in, const int* in_sizes, int n_in,
                              void* d_out, int out_size)
{
    const float* X      = (const float*)d_in[0];
    const float* adj    = (const float*)d_in[1];
    const float* wq_w   = (const float*)d_in[7];
    const float* wq_b   = (const float*)d_in[8];
    const float* wk_w   = (const float*)d_in[9];
    const float* wk_b   = (const float*)d_in[10];
    const float* trans_w= (const float*)d_in[11];
    const float* tgn_w  = (const float*)d_in[12];
    const float* tgn_b  = (const float*)d_in[13];
    const float* agg1_w = (const float*)d_in[14];
    const float* agg1_b = (const float*)d_in[15];
    const float* agg2_w = (const float*)d_in[16];
    const float* agg2_b = (const float*)d_in[17];
    const float* src_w  = (const float*)d_in[18];
    const float* src_b  = (const float*)d_in[19];
    const float* tgt_w  = (const float*)d_in[20];
    const float* tgt_b  = (const float*)d_in[21];
    const float* gz_w   = (const float*)d_in[22];
    const float* gz_b   = (const float*)d_in[23];
    const float* gr_w   = (const float*)d_in[24];
    const float* gr_b   = (const float*)d_in[25];
    const float* gc_w   = (const float*)d_in[26];
    const float* gc_b   = (const float*)d_in[27];
    const float* fcs_w  = (const float*)d_in[28];
    const float* fcs_b  = (const float*)d_in[29];
    const float* fcm_w  = (const float*)d_in[30];
    const float* fcm_b  = (const float*)d_in[31];
    float* out = (float*)d_out;

    Ptrs P;
    cudaGetSymbolAddress((void**)&P.hidden, g_hidden);
    cudaGetSymbolAddress((void**)&P.chainS, g_chainS);
    cudaGetSymbolAddress((void**)&P.gs, g_gs);
    cudaGetSymbolAddress((void**)&P.gt, g_gt);
    cudaGetSymbolAddress((void**)&P.ns, g_ns);
    cudaGetSymbolAddress((void**)&P.nt, g_nt);
    cudaGetSymbolAddress((void**)&P.adp, g_adp);
    cudaGetSymbolAddress((void**)&P.chainZ, g_chainZ);
    cudaGetSymbolAddress((void**)&P.zb, g_z);
    cudaGetSymbolAddress((void**)&P.rb, g_r);
    cudaGetSymbolAddress((void**)&P.Atgn, g_Atgn);
    cudaGetSymbolAddress((void**)&P.q, g_q);
    cudaGetSymbolAddress((void**)&P.k, g_k);
    cudaGetSymbolAddress((void**)&P.chainT, g_chainT);
    cudaGetSymbolAddress((void**)&P.tgnh, g_tgnh);
    cudaGetSymbolAddress((void**)&P.tar2, g_tar2);
    cudaGetSymbolAddress((void**)&P.gat, g_gat);

    // hidden = 0
    k_zero<<<DIV_UP(cB * cN * cH, 256), 256>>>(P.hidden, cB * cN * cH);

    // GRU warmup steps: t = 0,4,8,12,16
    for (int t = 0; t + 4 < cT; t += 4) {
        gru_step(X + (size_t)t * cN * cF, (size_t)cT * cN * cF, adj,
                 agg1_w, agg1_b, agg2_w, agg2_b, src_w, src_b, tgt_w, tgt_b,
                 gz_w, gz_b, gr_w, gr_b, gc_w, gc_b, P);
    }

    // attention block
    k_qk<<<DIV_UP(cB4 * cN * cD, 256), 256>>>(X, wq_w, wq_b, wk_w, wk_b, P.q, P.k, cN);
    k_attn<<<dim3(cN, cB4), 128>>>(P.q, P.k, trans_w, adj, P.Atgn, cN);

    // TGN gcn on src with A_tgn (batched A)
    k_pack_tgn<<<DIV_UP(cB4 * cN * cF, 256), 256>>>(X, P.chainT, cN);
    dim3 ggt(DIV_UP(cN, 32), cB4);
    k_gconv<<<ggt, 256>>>(P.chainT, LDT, cF, 0, 1, nullptr, 0, 0.f, P.Atgn, (size_t)cN * cN, kGA, cN);
    k_gconv<<<ggt, 256>>>(P.chainT, LDT, cF, 1, 2, nullptr, 0, 0.f, P.Atgn, (size_t)cN * cN, kGA, cN);
    k_matmul<<<DIV_UP(cB4 * cN * cTGN, 256), 256>>>(P.chainT, (size_t)cN * LDT, LDT, nullptr, 0,
        tgn_w, tgn_b, cTGN, P.tgnh, 2, nullptr, nullptr, nullptr, cB4, cN);
    k_reduce_t<<<DIV_UP(cB * cN * cTGN, 256), 256>>>(P.tgnh, P.tar2, cN);

    // gat = tar2 @ fcs
    k_matmul<<<DIV_UP(cB * cN * cF, 256), 256>>>(P.tar2, (size_t)cN * cTGN, cTGN, nullptr, 0,
        fcs_w, fcs_b, cF, P.gat, 0, nullptr, nullptr, nullptr, cB, cN);

    // final GRU step with gat
    gru_step(P.gat, (size_t)cN * cF, adj,
             agg1_w, agg1_b, agg2_w, agg2_b, src_w, src_b, tgt_w, tgt_b,
             gz_w, gz_b, gr_w, gr_b, gc_w, gc_b, P);

    // out[b, l, n] = (concat([tar2, hidden]) @ fcm_w + fcm_b), transposed store
    k_matmul<<<DIV_UP(cB * cN * cLEN, 256), 256>>>(P.tar2, (size_t)cN * cTGN, cTGN, P.hidden, cH,
        fcm_w, fcm_b, cLEN, out, 5, nullptr, nullptr, nullptr, cB, cN);
}

// round 2
// speedup vs baseline: 1.5588x; 1.5588x over previous
#include <cuda_runtime.h>
#include <math.h>

#define DIV_UP(a,b) (((a)+(b)-1)/(b))

// Problem constants
constexpr int cB   = 16;
constexpr int cT   = 24;
constexpr int cN   = 500;
constexpr int cF   = 2;
constexpr int cH   = 64;
constexpr int cD   = 8;
constexpr int cTGN = 32;
constexpr int cHYP = 16;
constexpr int cLEN = 24;
constexpr int cB4  = cB * 4;

constexpr float kAL = 0.05f, kBE = 0.95f, kGA = 0.95f, kTAU = 2.0f;

// padded chain layout: 3 slices of 72 floats each, row stride 216
constexpr int CP   = 72;
constexpr int LDCH = 216;

// ---------------- scratch ----------------
__device__ float g_chainS[cB * cN * LDCH];   // slice0 = hidden (persistent per call)
__device__ float g_chainZ[cB * cN * LDCH];
__device__ float g_chainC[cB * cN * LDCH];
__device__ float g_coef[(size_t)cB * cN * cN];
__device__ float g_ns[cB * cN * cHYP];
__device__ float g_nt[cB * cN * cHYP];
__device__ float g_z[cB * cN * cH];
__device__ float g_Atgn[(size_t)cB4 * cN * cN];
__device__ float g_q[cB * cN * cD];
__device__ float g_k[cB4 * cN * cD];
__device__ float g_chainT[cB4 * cN * 6];
__device__ float g_tar2[cB * cN * cTGN];
__device__ float g_gat[cB * cN * cF];

__device__ __forceinline__ float tanh_fast(float x) {
    float y;
    asm("tanh.approx.f32 %0, %1;" : "=f"(y) : "f"(x));
    return y;
}

// ---------------- kernels ----------------

__global__ void k_zero(float* p, int ntot) {
    int i = blockIdx.x * blockDim.x + threadIdx.x;
    if (i < ntot) p[i] = 0.f;
}

// Register-tiled graph conv:  buf[:,w,sOut*CP+c] = AL*buf[:,w,c] + sum_v coef[b,v,w]*buf[:,v,sIn*CP+c]
// block 192 thr = 6 warps; warp cg owns channels [12*cg, 12*cg+12); lane wi owns w = w0+2wi+{0,1}
__global__ __launch_bounds__(192) void k_gconv2(
    float* __restrict__ buf, int C, int sIn, int sOut,
    const float* __restrict__ A, size_t Abs, float scale, int n)
{
    const int b  = blockIdx.y;
    const int w0 = blockIdx.x * 64;
    const int tid = threadIdx.x;
    const int wi = tid & 31;
    const int cg = tid >> 5;
    const int c0 = cg * 12;

    __shared__ float cf[32][68];
    __shared__ float hsm[32][72];

    float acc[2][12];
#pragma unroll
    for (int k = 0; k < 2; k++)
#pragma unroll
        for (int j = 0; j < 12; j++) acc[k][j] = 0.f;

    const float* Ab = A + (size_t)b * Abs;
    const float* hb = buf + (size_t)b * n * LDCH + sIn * CP;

    for (int v0 = 0; v0 < n; v0 += 32) {
        // coef tile 32x64 (float4, scaled)
#pragma unroll
        for (int it = 0; it < 3; it++) {
            int idx = tid + it * 192;
            if (idx < 512) {
                int vi = idx >> 4, seg = idx & 15;
                int v = v0 + vi, w = w0 + seg * 4;
                float4 val = make_float4(0.f, 0.f, 0.f, 0.f);
                if (v < n) {
                    const float* ap = Ab + (size_t)v * n + w;
                    if (w + 3 < n) val = *(const float4*)ap;
                    else {
                        if (w     < n) val.x = ap[0];
                        if (w + 1 < n) val.y = ap[1];
                        if (w + 2 < n) val.z = ap[2];
                    }
                }
                val.x *= scale; val.y *= scale; val.z *= scale; val.w *= scale;
                *(float4*)&cf[vi][seg * 4] = val;
            }
        }
        // h tile 32x72 (float4)
#pragma unroll
        for (int it = 0; it < 3; it++) {
            int idx = tid + it * 192;
            int vi = idx / 18, seg = idx % 18;
            int v = v0 + vi;
            float4 val = make_float4(0.f, 0.f, 0.f, 0.f);
            if (v < n) val = *(const float4*)&hb[(size_t)v * LDCH + seg * 4];
            *(float4*)&hsm[vi][seg * 4] = val;
        }
        __syncthreads();

#pragma unroll
        for (int v = 0; v < 32; v++) {
            float2 cv = *(float2*)&cf[v][wi * 2];
            float4 ha = *(float4*)&hsm[v][c0];
            float4 hm = *(float4*)&hsm[v][c0 + 4];
            float4 hc = *(float4*)&hsm[v][c0 + 8];
            acc[0][0]  = fmaf(cv.x, ha.x, acc[0][0]);
            acc[0][1]  = fmaf(cv.x, ha.y, acc[0][1]);
            acc[0][2]  = fmaf(cv.x, ha.z, acc[0][2]);
            acc[0][3]  = fmaf(cv.x, ha.w, acc[0][3]);
            acc[0][4]  = fmaf(cv.x, hm.x, acc[0][4]);
            acc[0][5]  = fmaf(cv.x, hm.y, acc[0][5]);
            acc[0][6]  = fmaf(cv.x, hm.z, acc[0][6]);
            acc[0][7]  = fmaf(cv.x, hm.w, acc[0][7]);
            acc[0][8]  = fmaf(cv.x, hc.x, acc[0][8]);
            acc[0][9]  = fmaf(cv.x, hc.y, acc[0][9]);
            acc[0][10] = fmaf(cv.x, hc.z, acc[0][10]);
            acc[0][11] = fmaf(cv.x, hc.w, acc[0][11]);
            acc[1][0]  = fmaf(cv.y, ha.x, acc[1][0]);
            acc[1][1]  = fmaf(cv.y, ha.y, acc[1][1]);
            acc[1][2]  = fmaf(cv.y, ha.z, acc[1][2]);
            acc[1][3]  = fmaf(cv.y, ha.w, acc[1][3]);
            acc[1][4]  = fmaf(cv.y, hm.x, acc[1][4]);
            acc[1][5]  = fmaf(cv.y, hm.y, acc[1][5]);
            acc[1][6]  = fmaf(cv.y, hm.z, acc[1][6]);
            acc[1][7]  = fmaf(cv.y, hm.w, acc[1][7]);
            acc[1][8]  = fmaf(cv.y, hc.x, acc[1][8]);
            acc[1][9]  = fmaf(cv.y, hc.y, acc[1][9]);
            acc[1][10] = fmaf(cv.y, hc.z, acc[1][10]);
            acc[1][11] = fmaf(cv.y, hc.w, acc[1][11]);
        }
        __syncthreads();
    }

#pragma unroll
    for (int k = 0; k < 2; k++) {
        int w = w0 + wi * 2 + k;
        if (w < n) {
            float* op = buf + ((size_t)b * n + w) * LDCH;
#pragma unroll
            for (int j = 0; j < 12; j++) {
                int c = c0 + j;
                if (c < C) op[sOut * CP + c] = kAL * op[c] + acc[k][j];
            }
        }
    }
}

// C=2 graph conv for the TGN path (A already includes GA scaling)
__global__ __launch_bounds__(128) void k_gconv_f2(
    float* __restrict__ buf, int sIn, int sOut,
    const float* __restrict__ A, int n)
{
    int bt = blockIdx.y;
    int w0 = blockIdx.x * 128;
    int tid = threadIdx.x;
    __shared__ float As[32][132];
    __shared__ float2 xs[32];
    float a0 = 0.f, a1 = 0.f;
    const float* Ab = A + (size_t)bt * n * n;
    const float* hb = buf + (size_t)bt * n * 6 + sIn * 2;

    for (int v0 = 0; v0 < n; v0 += 32) {
#pragma unroll
        for (int it = 0; it < 8; it++) {
            int idx = tid + it * 128;
            int vi = idx >> 5, seg = idx & 31;
            int v = v0 + vi, w = w0 + seg * 4;
            float4 val = make_float4(0.f, 0.f, 0.f, 0.f);
            if (v < n) {
                const float* ap = Ab + (size_t)v * n + w;
                if (w + 3 < n) val = *(const float4*)ap;
                else {
                    if (w     < n) val.x = ap[0];
                    if (w + 1 < n) val.y = ap[1];
                    if (w + 2 < n) val.z = ap[2];
                }
            }
            *(float4*)&As[vi][seg * 4] = val;
        }
        if (tid < 32) {
            int v = v0 + tid;
            xs[tid] = (v < n) ? *(const float2*)&hb[(size_t)v * 6] : make_float2(0.f, 0.f);
        }
        __syncthreads();
#pragma unroll
        for (int v = 0; v < 32; v++) {
            float a = As[v][tid];
            float2 x = xs[v];
            a0 = fmaf(a, x.x, a0);
            a1 = fmaf(a, x.y, a1);
        }
        __syncthreads();
    }
    int w = w0 + tid;
    if (w < n) {
        float* op = buf + ((size_t)bt * n + w) * 6;
        op[sOut * 2]     = kAL * op[0] + a0;
        op[sOut * 2 + 1] = kAL * op[1] + a1;
    }
}

// pack step inputs: chainZ slice0 = [cur, hidden, 0pad]; chainC slice0 = [cur, 0.., 0pad]
__global__ void k_pack(const float* __restrict__ cur, size_t curBs,
                       const float* __restrict__ chainS,
                       float* __restrict__ chainZ, float* __restrict__ chainC, int n)
{
    int i = blockIdx.x * blockDim.x + threadIdx.x;
    int total = cB * n * CP;
    if (i >= total) return;
    int c = i % CP;
    int row = i / CP;
    int nn = row % n, b = row / n;
    float vz = 0.f, vc = 0.f;
    if (c < cF) {
        float x = cur[(size_t)b * curBs + (size_t)nn * cF + c];
        vz = x; vc = x;
    } else if (c < cF + cH) {
        vz = chainS[(size_t)row * LDCH + (c - cF)];
    }
    chainZ[(size_t)row * LDCH + c] = vz;
    chainC[(size_t)row * LDCH + c] = vc;
}

// fused: gs, gt (K=192 over chainS), then ns, nt
__global__ void k_agg(const float* __restrict__ cur, size_t curBs,
                      const float* __restrict__ chainS,
                      const float* __restrict__ a1w, const float* __restrict__ a1b,
                      const float* __restrict__ a2w, const float* __restrict__ a2b,
                      const float* __restrict__ sw, const float* __restrict__ sb,
                      const float* __restrict__ tw, const float* __restrict__ tb,
                      float* __restrict__ ns, float* __restrict__ nt, int n)
{
    int gid = blockIdx.x * blockDim.x + threadIdx.x;
    int total = cB * n * cHYP;
    if (gid >= total) return;
    int j = gid & (cHYP - 1);
    int row = gid / cHYP;
    int nn = row % n, b = row / n;

    const float* ch = chainS + (size_t)row * LDCH;
    float g1 = a1b[j], g2 = a2b[j];
#pragma unroll
    for (int s = 0; s < 3; s++) {
        const float* cs = ch + s * CP;
        const float* w1 = a1w + (size_t)s * cH * cHYP + j;
        const float* w2 = a2w + (size_t)s * cH * cHYP + j;
#pragma unroll 8
        for (int c = 0; c < cH; c++) {
            float v = cs[c];
            g1 = fmaf(v, w1[c * cHYP], g1);
            g2 = fmaf(v, w2[c * cHYP], g2);
        }
    }
    const float* xr = cur + (size_t)b * curBs + (size_t)nn * cF;
    float x0 = xr[0], x1 = xr[1];
    float ps = sb[j] + x0 * sw[j] + x1 * sw[cHYP + j];
    float pt = tb[j] + x0 * tw[j] + x1 * tw[cHYP + j];
    ns[gid] = tanhf(kTAU * ps * g1);
    nt[gid] = tanhf(kTAU * pt * g2);
}

// adp row + fold into combined gconv coefficient: coef = BE*adp + GA*adj
__global__ void k_adpcoef(const float* __restrict__ ns, const float* __restrict__ nt,
                          const float* __restrict__ adj, float* __restrict__ coef, int n)
{
    int b = blockIdx.y, i = blockIdx.x;
    int tid = threadIdx.x;
    __shared__ float nsr[16], ntr[16];
    __shared__ float rowbuf[512];
    __shared__ float red[128];

    if (tid < 16) {
        nsr[tid] = ns[((size_t)b * n + i) * 16 + tid];
        ntr[tid] = nt[((size_t)b * n + i) * 16 + tid];
    }
    __syncthreads();

    float lsum = 0.f;
    for (int m = tid; m < n; m += 128) {
        const float* nsm = ns + ((size_t)b * n + m) * 16;
        const float* ntm = nt + ((size_t)b * n + m) * 16;
        float a = 0.f;
#pragma unroll
        for (int c = 0; c < 16; c++) a += nsr[c] * ntm[c] - ntr[c] * nsm[c];
        float v = fmaxf(tanh_fast(kTAU * a), 0.f);
        if (m == i) v += 1.f;
        rowbuf[m] = v;
        lsum += v;
    }
    red[tid] = lsum; __syncthreads();
    for (int s = 64; s > 0; s >>= 1) { if (tid < s) red[tid] += red[tid + s]; __syncthreads(); }
    float inv = kBE / red[0];
    for (int m = tid; m < n; m += 128)
        coef[((size_t)b * n + i) * n + m] = rowbuf[m] * inv + kGA * adj[(size_t)i * n + m];
}

// fused z & r gates; writes r*hidden into chainC slice0
__global__ void k_gate2(const float* __restrict__ chainZ, const float* __restrict__ chainS,
                        float* __restrict__ chainC,
                        const float* __restrict__ zw, const float* __restrict__ zbv,
                        const float* __restrict__ rw, const float* __restrict__ rbv,
                        float* __restrict__ zout, int n)
{
    int gid = blockIdx.x * blockDim.x + threadIdx.x;
    int total = cB * n * cH;
    if (gid >= total) return;
    int m = gid & (cH - 1);
    int row = gid >> 6;

    const float* ch = chainZ + (size_t)row * LDCH;
    float az = zbv[m], ar = rbv[m];
#pragma unroll
    for (int s = 0; s < 3; s++) {
        const float* cs = ch + s * CP;
        const float* wz = zw + (size_t)s * 66 * cH + m;
        const float* wr = rw + (size_t)s * 66 * cH + m;
#pragma unroll 6
        for (int c = 0; c < 66; c++) {
            float v = cs[c];
            az = fmaf(v, wz[c * cH], az);
            ar = fmaf(v, wr[c * cH], ar);
        }
    }
    float z = 1.f / (1.f + expf(-az));
    float r = 1.f / (1.f + expf(-ar));
    zout[gid] = z;
    chainC[(size_t)row * LDCH + cF + m] = r * chainS[(size_t)row * LDCH + m];
}

// fused c-gate + GRU hidden update (writes hidden home = chainS slice0)
__global__ void k_gcu(const float* __restrict__ chainC, float* __restrict__ chainS,
                      const float* __restrict__ zbuf,
                      const float* __restrict__ cw, const float* __restrict__ cbv, int n)
{
    int gid = blockIdx.x * blockDim.x + threadIdx.x;
    int total = cB * n * cH;
    if (gid >= total) return;
    int m = gid & (cH - 1);
    int row = gid >> 6;

    const float* ch = chainC + (size_t)row * LDCH;
    float ac = cbv[m];
#pragma unroll
    for (int s = 0; s < 3; s++) {
        const float* cs = ch + s * CP;
        const float* wc = cw + (size_t)s * 66 * cH + m;
#pragma unroll 6
        for (int c = 0; c < 66; c++)
            ac = fmaf(cs[c], wc[c * cH], ac);
    }
    float cval = tanhf(ac);
    float z = zbuf[gid];
    float* hp = chainS + (size_t)row * LDCH + m;
    *hp = z * (*hp) + (1.f - z) * cval;
}

// q/k projections for attention
__global__ void k_qk(const float* __restrict__ X,
                     const float* __restrict__ wqw, const float* __restrict__ wqb,
                     const float* __restrict__ wkw, const float* __restrict__ wkb,
                     float* __restrict__ q, float* __restrict__ kk, int n)
{
    int i = blockIdx.x * blockDim.x + threadIdx.x;
    int total = cB4 * n * cD;
    if (i >= total) return;
    int d = i % cD;
    int row = i / cD;
    int nn = row % n, bt = row / n;
    int b = bt >> 2, t = bt & 3;
    const float* xr = X + ((((size_t)b * cT) + (cT - 4) + t) * n + nn) * cF;
    kk[i] = wkb[d] + xr[0] * wkw[d] + xr[1] * wkw[cD + d];
    if (t == 3)
        q[((size_t)b * n + nn) * cD + d] = wqb[d] + xr[0] * wqw[d] + xr[1] * wqw[cD + d];
}

// scores + softmax + A_tgn = GA*(adj + attn)
__global__ void k_attn(const float* __restrict__ q, const float* __restrict__ kk,
                       const float* __restrict__ tw, const float* __restrict__ adj,
                       float* __restrict__ Atgn, int n)
{
    int bt = blockIdx.y, i = blockIdx.x;
    int b = bt >> 2;
    int tid = threadIdx.x;
    __shared__ float qd[8], twv[8];
    __shared__ float rowbuf[512];
    __shared__ float red[128];

    if (tid < 8) {
        qd[tid]  = q[((size_t)b * n + i) * 8 + tid];
        twv[tid] = tw[tid];
    }
    __syncthreads();

    float lmax = -1e30f;
    for (int j = tid; j < n; j += 128) {
        const float* kj = kk + ((size_t)bt * n + j) * 8;
        float s = 0.f;
#pragma unroll
        for (int d = 0; d < 8; d++) s = fmaf(tanh_fast(qd[d] + kj[d]), twv[d], s);
        rowbuf[j] = s;
        lmax = fmaxf(lmax, s);
    }
    red[tid] = lmax; __syncthreads();
    for (int s = 64; s > 0; s >>= 1) { if (tid < s) red[tid] = fmaxf(red[tid], red[tid + s]); __syncthreads(); }
    float gmax = red[0];
    __syncthreads();

    float lsum = 0.f;
    for (int j = tid; j < n; j += 128) {
        float e = __expf(rowbuf[j] - gmax);
        rowbuf[j] = e; lsum += e;
    }
    red[tid] = lsum; __syncthreads();
    for (int s = 64; s > 0; s >>= 1) { if (tid < s) red[tid] += red[tid + s]; __syncthreads(); }
    float inv = 1.f / red[0];
    for (int j = tid; j < n; j += 128)
        Atgn[((size_t)bt * n + i) * n + j] = kGA * (adj[(size_t)i * n + j] + rowbuf[j] * inv);
}

__global__ void k_pack_tgn(const float* __restrict__ X, float* __restrict__ chainT, int n)
{
    int i = blockIdx.x * blockDim.x + threadIdx.x;
    int total = cB4 * n * cF;
    if (i >= total) return;
    int f = i % cF;
    int row = i / cF;
    int nn = row % n, bt = row / n;
    int b = bt >> 2, t = bt & 3;
    chainT[(size_t)row * 6 + f] =
        X[((((size_t)b * cT) + (cT - 4) + t) * n + nn) * cF + f];
}

// fused tgn matmul + relu + sum over t
__global__ void k_tgn_out(const float* __restrict__ chainT,
                          const float* __restrict__ tw, const float* __restrict__ tb,
                          float* __restrict__ tar2, int n)
{
    int gid = blockIdx.x * blockDim.x + threadIdx.x;
    int total = cB * n * cTGN;
    if (gid >= total) return;
    int m = gid & (cTGN - 1);
    int row = gid / cTGN;
    int nn = row % n, b = row / n;
    float tot = 0.f;
#pragma unroll
    for (int t = 0; t < 4; t++) {
        const float* cr = chainT + (((size_t)(b * 4 + t) * n) + nn) * 6;
        float s = tb[m];
#pragma unroll
        for (int k = 0; k < 6; k++)
            s = fmaf(cr[k], tw[k * cTGN + m], s);
        tot += fmaxf(s, 0.f);
    }
    tar2[gid] = tot;
}

// generic small FC: in1 (sliced) [+ in2 dense-ish]; mode 0 plain, 1 transposed store
__global__ void k_fc(const float* __restrict__ in1, int ld1, int sw1, int C1, int ns1,
                     const float* __restrict__ in2, int ld2, int C2,
                     const float* __restrict__ W, const float* __restrict__ Bv, int M,
                     float* __restrict__ out, int mode, int n, int rows)
{
    int gid = blockIdx.x * blockDim.x + threadIdx.x;
    if (gid >= rows * M) return;
    int m = gid % M;
    int row = gid / M;
    float acc = Bv[m];
    int k = 0;
    const float* r1 = in1 + (size_t)row * ld1;
    for (int s = 0; s < ns1; s++)
        for (int c = 0; c < C1; c++)
            acc = fmaf(r1[s * sw1 + c], W[(k++) * M + m], acc);
    if (in2) {
        const float* r2 = in2 + (size_t)row * ld2;
        for (int c = 0; c < C2; c++)
            acc = fmaf(r2[c], W[(k++) * M + m], acc);
    }
    if (mode == 0) out[(size_t)row * M + m] = acc;
    else {
        int nn = row % n, b = row / n;
        out[((size_t)b * M + m) * n + nn] = acc;
    }
}

// ---------------- host orchestration ----------------

struct Ptrs {
    float *chainS, *chainZ, *chainC, *coef, *ns, *nt, *z;
    float *Atgn, *q, *k, *chainT, *tar2, *gat;
};

static void gru_step(const float* cur, size_t curBs, const float* adj,
                     const float* a1w, const float* a1b, const float* a2w, const float* a2b,
                     const float* sw, const float* sb, const float* tw, const float* tb,
                     const float* zw, const float* zb, const float* rw, const float* rb,
                     const float* cw, const float* cb, const Ptrs& P)
{
    const int n = cN;
    dim3 gg(DIV_UP(n, 64), cB);

    k_pack<<<DIV_UP(cB * n * CP, 256), 256>>>(cur, curBs, P.chainS, P.chainZ, P.chainC, n);

    k_gconv2<<<gg, 192>>>(P.chainS, cH, 0, 1, adj, 0, kGA, n);
    k_gconv2<<<gg, 192>>>(P.chainS, cH, 1, 2, adj, 0, kGA, n);

    k_agg<<<DIV_UP(cB * n * cHYP, 256), 256>>>(cur, curBs, P.chainS,
        a1w, a1b, a2w, a2b, sw, sb, tw, tb, P.ns, P.nt, n);

    k_adpcoef<<<dim3(n, cB), 128>>>(P.ns, P.nt, adj, P.coef, n);

    k_gconv2<<<gg, 192>>>(P.chainZ, cF + cH, 0, 1, P.coef, (size_t)n * n, 1.f, n);
    k_gconv2<<<gg, 192>>>(P.chainZ, cF + cH, 1, 2, P.coef, (size_t)n * n, 1.f, n);

    k_gate2<<<DIV_UP(cB * n * cH, 256), 256>>>(P.chainZ, P.chainS, P.chainC,
        zw, zb, rw, rb, P.z, n);

    k_gconv2<<<gg, 192>>>(P.chainC, cF + cH, 0, 1, P.coef, (size_t)n * n, 1.f, n);
    k_gconv2<<<gg, 192>>>(P.chainC, cF + cH, 1, 2, P.coef, (size_t)n * n, 1.f, n);

    k_gcu<<<DIV_UP(cB * n * cH, 256), 256>>>(P.chainC, P.chainS, P.z, cw, cb, n);
}

extern "C" void kernel_launch(void* const* d_in, const int* in_sizes, int n_in,
                              void* d_out, int out_size)
{
    const float* X      = (const float*)d_in[0];
    const float* adj    = (const float*)d_in[1];
    const float* wq_w   = (const float*)d_in[7];
    const float* wq_b   = (const float*)d_in[8];
    const float* wk_w   = (const float*)d_in[9];
    const float* wk_b   = (const float*)d_in[10];
    const float* trans_w= (const float*)d_in[11];
    const float* tgn_w  = (const float*)d_in[12];
    const float* tgn_b  = (const float*)d_in[13];
    const float* agg1_w = (const float*)d_in[14];
    const float* agg1_b = (const float*)d_in[15];
    const float* agg2_w = (const float*)d_in[16];
    const float* agg2_b = (const float*)d_in[17];
    const float* src_w  = (const float*)d_in[18];
    const float* src_b  = (const float*)d_in[19];
    const float* tgt_w  = (const float*)d_in[20];
    const float* tgt_b  = (const float*)d_in[21];
    const float* gz_w   = (const float*)d_in[22];
    const float* gz_b   = (const float*)d_in[23];
    const float* gr_w   = (const float*)d_in[24];
    const float* gr_b   = (const float*)d_in[25];
    const float* gc_w   = (const float*)d_in[26];
    const float* gc_b   = (const float*)d_in[27];
    const float* fcs_w  = (const float*)d_in[28];
    const float* fcs_b  = (const float*)d_in[29];
    const float* fcm_w  = (const float*)d_in[30];
    const float* fcm_b  = (const float*)d_in[31];
    float* out = (float*)d_out;

    Ptrs P;
    cudaGetSymbolAddress((void**)&P.chainS, g_chainS);
    cudaGetSymbolAddress((void**)&P.chainZ, g_chainZ);
    cudaGetSymbolAddress((void**)&P.chainC, g_chainC);
    cudaGetSymbolAddress((void**)&P.coef,   g_coef);
    cudaGetSymbolAddress((void**)&P.ns,     g_ns);
    cudaGetSymbolAddress((void**)&P.nt,     g_nt);
    cudaGetSymbolAddress((void**)&P.z,      g_z);
    cudaGetSymbolAddress((void**)&P.Atgn,   g_Atgn);
    cudaGetSymbolAddress((void**)&P.q,      g_q);
    cudaGetSymbolAddress((void**)&P.k,      g_k);
    cudaGetSymbolAddress((void**)&P.chainT, g_chainT);
    cudaGetSymbolAddress((void**)&P.tar2,   g_tar2);
    cudaGetSymbolAddress((void**)&P.gat,    g_gat);

    // hidden (chainS) = 0 — deterministic per call
    k_zero<<<DIV_UP(cB * cN * LDCH, 256), 256>>>(P.chainS, cB * cN * LDCH);

    // warmup GRU steps: t = 0,4,8,12,16
    for (int t = 0; t + 4 < cT; t += 4) {
        gru_step(X + (size_t)t * cN * cF, (size_t)cT * cN * cF, adj,
                 agg1_w, agg1_b, agg2_w, agg2_b, src_w, src_b, tgt_w, tgt_b,
                 gz_w, gz_b, gr_w, gr_b, gc_w, gc_b, P);
    }

    // attention block
    k_qk<<<DIV_UP(cB4 * cN * cD, 256), 256>>>(X, wq_w, wq_b, wk_w, wk_b, P.q, P.k, cN);
    k_attn<<<dim3(cN, cB4), 128>>>(P.q, P.k, trans_w, adj, P.Atgn, cN);

    // TGN gcn (C=2) with A_tgn
    k_pack_tgn<<<DIV_UP(cB4 * cN * cF, 256), 256>>>(X, P.chainT, cN);
    dim3 ggt(DIV_UP(cN, 128), cB4);
    k_gconv_f2<<<ggt, 128>>>(P.chainT, 0, 1, P.Atgn, cN);
    k_gconv_f2<<<ggt, 128>>>(P.chainT, 1, 2, P.Atgn, cN);
    k_tgn_out<<<DIV_UP(cB * cN * cTGN, 256), 256>>>(P.chainT, tgn_w, tgn_b, P.tar2, cN);

    // gat = tar2 @ fcs
    k_fc<<<DIV_UP(cB * cN * cF, 256), 256>>>(P.tar2, cTGN, 0, cTGN, 1,
        nullptr, 0, 0, fcs_w, fcs_b, cF, P.gat, 0, cN, cB * cN);

    // final GRU step
    gru_step(P.gat, (size_t)cN * cF, adj,
             agg1_w, agg1_b, agg2_w, agg2_b, src_w, src_b, tgt_w, tgt_b,
             gz_w, gz_b, gr_w, gr_b, gc_w, gc_b, P);

    // out[b, l, n] = concat([tar2, hidden]) @ fcm_w + fcm_b (transposed store)
    k_fc<<<DIV_UP(cB * cN * cLEN, 256), 256>>>(P.tar2, cTGN, 0, cTGN, 1,
        P.chainS, LDCH, cH, fcm_w, fcm_b, cLEN, out, 1, cN, cB * cN);
}

// round 3
// speedup vs baseline: 2.3526x; 1.5092x over previous
#include <cuda_runtime.h>
#include <math.h>

#define DIV_UP(a,b) (((a)+(b)-1)/(b))

// Problem constants
constexpr int cB   = 16;
constexpr int cT   = 24;
constexpr int cN   = 500;
constexpr int cF   = 2;
constexpr int cH   = 64;
constexpr int cD   = 8;
constexpr int cTGN = 32;
constexpr int cHYP = 16;
constexpr int cLEN = 24;
constexpr int cB4  = cB * 4;

constexpr float kAL = 0.05f, kBE = 0.95f, kGA = 0.95f, kTAU = 2.0f;

// padded chain layout: 3 slices of 72 floats each, row stride 216
constexpr int CP   = 72;
constexpr int LDCH = 216;

// ---------------- scratch ----------------
__device__ float g_chainS[cB * cN * LDCH];   // slice0 = hidden (persistent per call)
__device__ float g_chainZ[cB * cN * LDCH];
__device__ float g_chainC[cB * cN * LDCH];
__device__ float g_coef[(size_t)cB * cN * cN];
__device__ float g_ns[cB * cN * cHYP];
__device__ float g_nt[cB * cN * cHYP];
__device__ float g_z[cB * cN * cH];
__device__ float g_Atgn[(size_t)cB4 * cN * cN];
__device__ float g_q[cB * cN * cD];
__device__ float g_k[cB4 * cN * cD];
__device__ float g_chainT[cB4 * cN * 6];
__device__ float g_tar2[cB * cN * cTGN];
__device__ float g_gat[cB * cN * cF];

__device__ __forceinline__ float tanh_fast(float x) {
    float y;
    asm("tanh.approx.f32 %0, %1;" : "=f"(y) : "f"(x));
    return y;
}
__device__ __forceinline__ float sigmoid_fast(float x) {
    return 1.f / (1.f + __expf(-x));
}

// ---------------- kernels ----------------

__global__ void k_zero(float* p, int ntot) {
    int i = blockIdx.x * blockDim.x + threadIdx.x;
    if (i < ntot) p[i] = 0.f;
}

// Register-tiled graph conv: buf[:,w,sOut*CP+c] = AL*buf[:,w,c] + sum_v coef[b,v,w]*buf[:,v,sIn*CP+c]
// block 192 thr = 6 warps; warp cg owns channels [12*cg, 12*cg+12); lane wi owns w = w0+wi
// tile: 32 w x 72 c per block -> grid (16, B) = 256 blocks
__global__ __launch_bounds__(192) void k_gconv2(
    float* __restrict__ buf, int C, int sIn, int sOut,
    const float* __restrict__ A, size_t Abs, float scale, int n)
{
    const int b  = blockIdx.y;
    const int w0 = blockIdx.x * 32;
    const int tid = threadIdx.x;
    const int wi = tid & 31;
    const int cg = tid >> 5;              // 0..5
    const int c0 = cg * 12;

    __shared__ float cf[32][36];          // [v][w], padded
    __shared__ float hs[32][76];          // [v][c], padded

    float acc[12];
#pragma unroll
    for (int j = 0; j < 12; j++) acc[j] = 0.f;

    const float* Ab = A + (size_t)b * Abs;
    const float* hb = buf + (size_t)b * n * LDCH + sIn * CP;

    for (int v0 = 0; v0 < n; v0 += 32) {
        // coef tile 32x32 = 256 float4
#pragma unroll
        for (int it = 0; it < 2; it++) {
            int idx = tid + it * 192;
            if (idx < 256) {
                int vi = idx >> 3, seg = idx & 7;
                int v = v0 + vi, w = w0 + seg * 4;
                float4 val = make_float4(0.f, 0.f, 0.f, 0.f);
                if (v < n) {
                    const float* ap = Ab + (size_t)v * n + w;
                    if (w + 3 < n) val = *(const float4*)ap;
                    else {
                        if (w     < n) val.x = ap[0];
                        if (w + 1 < n) val.y = ap[1];
                        if (w + 2 < n) val.z = ap[2];
                    }
                }
                val.x *= scale; val.y *= scale; val.z *= scale; val.w *= scale;
                *(float4*)&cf[vi][seg * 4] = val;
            }
        }
        // h tile 32x72 = 576 float4, exactly 3 per thread
#pragma unroll
        for (int it = 0; it < 3; it++) {
            int idx = tid + it * 192;
            int vi = idx / 18, seg = idx % 18;
            int v = v0 + vi;
            float4 val = make_float4(0.f, 0.f, 0.f, 0.f);
            if (v < n) val = *(const float4*)&hb[(size_t)v * LDCH + seg * 4];
            *(float4*)&hs[vi][seg * 4] = val;
        }
        __syncthreads();

#pragma unroll
        for (int v = 0; v < 32; v++) {
            float cv = cf[v][wi];
            float4 ha = *(float4*)&hs[v][c0];
            float4 hm = *(float4*)&hs[v][c0 + 4];
            float4 hc = *(float4*)&hs[v][c0 + 8];
            acc[0]  = fmaf(cv, ha.x, acc[0]);
            acc[1]  = fmaf(cv, ha.y, acc[1]);
            acc[2]  = fmaf(cv, ha.z, acc[2]);
            acc[3]  = fmaf(cv, ha.w, acc[3]);
            acc[4]  = fmaf(cv, hm.x, acc[4]);
            acc[5]  = fmaf(cv, hm.y, acc[5]);
            acc[6]  = fmaf(cv, hm.z, acc[6]);
            acc[7]  = fmaf(cv, hm.w, acc[7]);
            acc[8]  = fmaf(cv, hc.x, acc[8]);
            acc[9]  = fmaf(cv, hc.y, acc[9]);
            acc[10] = fmaf(cv, hc.z, acc[10]);
            acc[11] = fmaf(cv, hc.w, acc[11]);
        }
        __syncthreads();
    }

    int w = w0 + wi;
    if (w < n) {
        float* op = buf + ((size_t)b * n + w) * LDCH;
#pragma unroll
        for (int j = 0; j < 12; j++) {
            int c = c0 + j;
            if (c < C) op[sOut * CP + c] = kAL * op[c] + acc[j];
        }
    }
}

// C=2 graph conv for the TGN path (A already includes GA scaling)
__global__ __launch_bounds__(128) void k_gconv_f2(
    float* __restrict__ buf, int sIn, int sOut,
    const float* __restrict__ A, int n)
{
    int bt = blockIdx.y;
    int w0 = blockIdx.x * 128;
    int tid = threadIdx.x;
    __shared__ float As[32][132];
    __shared__ float2 xs[32];
    float a0 = 0.f, a1 = 0.f;
    const float* Ab = A + (size_t)bt * n * n;
    const float* hb = buf + (size_t)bt * n * 6 + sIn * 2;

    for (int v0 = 0; v0 < n; v0 += 32) {
#pragma unroll
        for (int it = 0; it < 8; it++) {
            int idx = tid + it * 128;
            int vi = idx >> 5, seg = idx & 31;
            int v = v0 + vi, w = w0 + seg * 4;
            float4 val = make_float4(0.f, 0.f, 0.f, 0.f);
            if (v < n) {
                const float* ap = Ab + (size_t)v * n + w;
                if (w + 3 < n) val = *(const float4*)ap;
                else {
                    if (w     < n) val.x = ap[0];
                    if (w + 1 < n) val.y = ap[1];
                    if (w + 2 < n) val.z = ap[2];
                }
            }
            *(float4*)&As[vi][seg * 4] = val;
        }
        if (tid < 32) {
            int v = v0 + tid;
            xs[tid] = (v < n) ? *(const float2*)&hb[(size_t)v * 6] : make_float2(0.f, 0.f);
        }
        __syncthreads();
#pragma unroll
        for (int v = 0; v < 32; v++) {
            float a = As[v][tid];
            float2 x = xs[v];
            a0 = fmaf(a, x.x, a0);
            a1 = fmaf(a, x.y, a1);
        }
        __syncthreads();
    }
    int w = w0 + tid;
    if (w < n) {
        float* op = buf + ((size_t)bt * n + w) * 6;
        op[sOut * 2]     = kAL * op[0] + a0;
        op[sOut * 2 + 1] = kAL * op[1] + a1;
    }
}

// pack step inputs: chainZ slice0 = [cur, hidden, 0pad]; chainC slice0 = [cur, 0..]
__global__ void k_pack(const float* __restrict__ cur, size_t curBs,
                       const float* __restrict__ chainS,
                       float* __restrict__ chainZ, float* __restrict__ chainC, int n)
{
    int i = blockIdx.x * blockDim.x + threadIdx.x;
    int total = cB * n * CP;
    if (i >= total) return;
    int c = i % CP;
    int row = i / CP;
    int nn = row % n, b = row / n;
    float vz = 0.f, vc = 0.f;
    if (c < cF) {
        float x = cur[(size_t)b * curBs + (size_t)nn * cF + c];
        vz = x; vc = x;
    } else if (c < cF + cH) {
        vz = chainS[(size_t)row * LDCH + (c - cF)];
    }
    chainZ[(size_t)row * LDCH + c] = vz;
    chainC[(size_t)row * LDCH + c] = vc;
}

// fused: gs, gt (K=192 over chainS), then ns, nt
__global__ void k_agg(const float* __restrict__ cur, size_t curBs,
                      const float* __restrict__ chainS,
                      const float* __restrict__ a1w, const float* __restrict__ a1b,
                      const float* __restrict__ a2w, const float* __restrict__ a2b,
                      const float* __restrict__ sw, const float* __restrict__ sb,
                      const float* __restrict__ tw, const float* __restrict__ tb,
                      float* __restrict__ ns, float* __restrict__ nt, int n)
{
    int gid = blockIdx.x * blockDim.x + threadIdx.x;
    int total = cB * n * cHYP;
    if (gid >= total) return;
    int j = gid & (cHYP - 1);
    int row = gid / cHYP;
    int nn = row % n, b = row / n;

    const float* ch = chainS + (size_t)row * LDCH;
    float g1 = a1b[j], g2 = a2b[j];
#pragma unroll
    for (int s = 0; s < 3; s++) {
        const float* cs = ch + s * CP;
        const float* w1 = a1w + (size_t)s * cH * cHYP + j;
        const float* w2 = a2w + (size_t)s * cH * cHYP + j;
#pragma unroll 8
        for (int c = 0; c < cH; c++) {
            float v = cs[c];
            g1 = fmaf(v, w1[c * cHYP], g1);
            g2 = fmaf(v, w2[c * cHYP], g2);
        }
    }
    const float* xr = cur + (size_t)b * curBs + (size_t)nn * cF;
    float x0 = xr[0], x1 = xr[1];
    float ps = sb[j] + x0 * sw[j] + x1 * sw[cHYP + j];
    float pt = tb[j] + x0 * tw[j] + x1 * tw[cHYP + j];
    ns[gid] = tanh_fast(kTAU * ps * g1);
    nt[gid] = tanh_fast(kTAU * pt * g2);
}

// adp rows (4 per block) folded into combined gconv coefficient: coef = BE*adp + GA*adj
__global__ __launch_bounds__(128) void k_adpcoef(
    const float* __restrict__ ns, const float* __restrict__ nt,
    const float* __restrict__ adj, float* __restrict__ coef, int n)
{
    int b = blockIdx.y, i0 = blockIdx.x * 4;
    int tid = threadIdx.x;
    int lane = tid & 31, warp = tid >> 5;

    __shared__ float nsr[4][16], ntr[4][16];
    __shared__ float rowbuf[4][512];
    __shared__ float red[4][4];
    __shared__ float invs[4];

    if (tid < 64) {
        int ii = tid >> 4, c = tid & 15;
        nsr[ii][c] = ns[((size_t)b * n + i0 + ii) * 16 + c];
    } else {
        int t = tid - 64;
        int ii = t >> 4, c = t & 15;
        ntr[ii][c] = nt[((size_t)b * n + i0 + ii) * 16 + c];
    }
    __syncthreads();

    float lsum[4] = {0.f, 0.f, 0.f, 0.f};
    for (int m = tid; m < n; m += 128) {
        const float4* nsm = (const float4*)(ns + ((size_t)b * n + m) * 16);
        const float4* ntm = (const float4*)(nt + ((size_t)b * n + m) * 16);
        float4 s0 = nsm[0], s1 = nsm[1], s2 = nsm[2], s3 = nsm[3];
        float4 t0 = ntm[0], t1 = ntm[1], t2 = ntm[2], t3 = ntm[3];
        float sm[16] = {s0.x,s0.y,s0.z,s0.w, s1.x,s1.y,s1.z,s1.w,
                        s2.x,s2.y,s2.z,s2.w, s3.x,s3.y,s3.z,s3.w};
        float tm[16] = {t0.x,t0.y,t0.z,t0.w, t1.x,t1.y,t1.z,t1.w,
                        t2.x,t2.y,t2.z,t2.w, t3.x,t3.y,t3.z,t3.w};
#pragma unroll
        for (int ii = 0; ii < 4; ii++) {
            float a = 0.f;
#pragma unroll
            for (int c = 0; c < 16; c++)
                a += nsr[ii][c] * tm[c] - ntr[ii][c] * sm[c];
            float v = fmaxf(tanh_fast(kTAU * a), 0.f);
            if (m == i0 + ii) v += 1.f;
            rowbuf[ii][m] = v;
            lsum[ii] += v;
        }
    }
#pragma unroll
    for (int ii = 0; ii < 4; ii++) {
        float s = lsum[ii];
#pragma unroll
        for (int o = 16; o > 0; o >>= 1) s += __shfl_xor_sync(0xffffffffu, s, o);
        if (lane == 0) red[ii][warp] = s;
    }
    __syncthreads();
    if (tid < 4)
        invs[tid] = kBE / (red[tid][0] + red[tid][1] + red[tid][2] + red[tid][3]);
    __syncthreads();

    for (int m = tid; m < n; m += 128) {
#pragma unroll
        for (int ii = 0; ii < 4; ii++)
            coef[((size_t)b * n + i0 + ii) * n + m] =
                rowbuf[ii][m] * invs[ii] + kGA * adj[(size_t)(i0 + ii) * n + m];
    }
}

// fused z & r gates; writes r*hidden into chainC slice0
__global__ void k_gate2(const float* __restrict__ chainZ, const float* __restrict__ chainS,
                        float* __restrict__ chainC,
                        const float* __restrict__ zw, const float* __restrict__ zbv,
                        const float* __restrict__ rw, const float* __restrict__ rbv,
                        float* __restrict__ zout, int n)
{
    int gid = blockIdx.x * blockDim.x + threadIdx.x;
    int total = cB * n * cH;
    if (gid >= total) return;
    int m = gid & (cH - 1);
    int row = gid >> 6;

    const float* ch = chainZ + (size_t)row * LDCH;
    float az = zbv[m], ar = rbv[m];
#pragma unroll
    for (int s = 0; s < 3; s++) {
        const float* cs = ch + s * CP;
        const float* wz = zw + (size_t)s * 66 * cH + m;
        const float* wr = rw + (size_t)s * 66 * cH + m;
#pragma unroll 6
        for (int c = 0; c < 66; c++) {
            float v = cs[c];
            az = fmaf(v, wz[c * cH], az);
            ar = fmaf(v, wr[c * cH], ar);
        }
    }
    float z = sigmoid_fast(az);
    float r = sigmoid_fast(ar);
    zout[gid] = z;
    chainC[(size_t)row * LDCH + cF + m] = r * chainS[(size_t)row * LDCH + m];
}

// fused c-gate + GRU hidden update; optionally packs next step inputs
__global__ void k_gcu(const float* __restrict__ chainC, float* __restrict__ chainS,
                      const float* __restrict__ zbuf,
                      const float* __restrict__ cw, const float* __restrict__ cbv,
                      const float* __restrict__ nextCur, size_t nextBs,
                      float* __restrict__ chainZ, float* __restrict__ chainCp, int n)
{
    int gid = blockIdx.x * blockDim.x + threadIdx.x;
    int total = cB * n * cH;
    if (gid >= total) return;
    int m = gid & (cH - 1);
    int row = gid >> 6;

    const float* ch = chainC + (size_t)row * LDCH;
    float ac = cbv[m];
#pragma unroll
    for (int s = 0; s < 3; s++) {
        const float* cs = ch + s * CP;
        const float* wc = cw + (size_t)s * 66 * cH + m;
#pragma unroll 6
        for (int c = 0; c < 66; c++)
            ac = fmaf(cs[c], wc[c * cH], ac);
    }
    float cval = tanh_fast(ac);
    float z = zbuf[gid];
    float* hp = chainS + (size_t)row * LDCH + m;
    float hnew = z * (*hp) + (1.f - z) * cval;
    *hp = hnew;
    if (nextCur) {
        chainZ[(size_t)row * LDCH + cF + m] = hnew;
        if (m < cF) {
            int nn = row % n, b = row / n;
            float x = nextCur[(size_t)b * nextBs + (size_t)nn * cF + m];
            chainZ[(size_t)row * LDCH + m]  = x;
            chainCp[(size_t)row * LDCH + m] = x;
        }
    }
}

// q/k projections for attention
__global__ void k_qk(const float* __restrict__ X,
                     const float* __restrict__ wqw, const float* __restrict__ wqb,
                     const float* __restrict__ wkw, const float* __restrict__ wkb,
                     float* __restrict__ q, float* __restrict__ kk, int n)
{
    int i = blockIdx.x * blockDim.x + threadIdx.x;
    int total = cB4 * n * cD;
    if (i >= total) return;
    int d = i % cD;
    int row = i / cD;
    int nn = row % n, bt = row / n;
    int b = bt >> 2, t = bt & 3;
    const float* xr = X + ((((size_t)b * cT) + (cT - 4) + t) * n + nn) * cF;
    kk[i] = wkb[d] + xr[0] * wkw[d] + xr[1] * wkw[cD + d];
    if (t == 3)
        q[((size_t)b * n + nn) * cD + d] = wqb[d] + xr[0] * wqw[d] + xr[1] * wqw[cD + d];
}

// scores + softmax + A_tgn = GA*(adj + attn); 4 rows i per block
__global__ __launch_bounds__(128) void k_attn(
    const float* __restrict__ q, const float* __restrict__ kk,
    const float* __restrict__ tw, const float* __restrict__ adj,
    float* __restrict__ Atgn, int n)
{
    int bt = blockIdx.y, i0 = blockIdx.x * 4;
    int b = bt >> 2;
    int tid = threadIdx.x;
    int lane = tid & 31, warp = tid >> 5;

    __shared__ float qd[4][8], twv[8];
    __shared__ float rowbuf[4][512];
    __shared__ float red[4][4];
    __shared__ float scal[4];

    if (tid < 32) {
        int ii = tid >> 3, d = tid & 7;
        qd[ii][d] = q[((size_t)b * n + i0 + ii) * 8 + d];
    } else if (tid < 40) {
        twv[tid - 32] = tw[tid - 32];
    }
    __syncthreads();

    float lmax[4] = {-1e30f, -1e30f, -1e30f, -1e30f};
    for (int j = tid; j < n; j += 128) {
        const float4* kj4 = (const float4*)(kk + ((size_t)bt * n + j) * 8);
        float4 k0 = kj4[0], k1 = kj4[1];
        float kj[8] = {k0.x,k0.y,k0.z,k0.w, k1.x,k1.y,k1.z,k1.w};
#pragma unroll
        for (int ii = 0; ii < 4; ii++) {
            float s = 0.f;
#pragma unroll
            for (int d = 0; d < 8; d++)
                s = fmaf(tanh_fast(qd[ii][d] + kj[d]), twv[d], s);
            rowbuf[ii][j] = s;
            lmax[ii] = fmaxf(lmax[ii], s);
        }
    }
#pragma unroll
    for (int ii = 0; ii < 4; ii++) {
        float s = lmax[ii];
#pragma unroll
        for (int o = 16; o > 0; o >>= 1) s = fmaxf(s, __shfl_xor_sync(0xffffffffu, s, o));
        if (lane == 0) red[ii][warp] = s;
    }
    __syncthreads();
    if (tid < 4)
        scal[tid] = fmaxf(fmaxf(red[tid][0], red[tid][1]), fmaxf(red[tid][2], red[tid][3]));
    __syncthreads();

    float lsum[4] = {0.f, 0.f, 0.f, 0.f};
    for (int j = tid; j < n; j += 128) {
#pragma unroll
        for (int ii = 0; ii < 4; ii++) {
            float e = __expf(rowbuf[ii][j] - scal[ii]);
            rowbuf[ii][j] = e;
            lsum[ii] += e;
        }
    }
#pragma unroll
    for (int ii = 0; ii < 4; ii++) {
        float s = lsum[ii];
#pragma unroll
        for (int o = 16; o > 0; o >>= 1) s += __shfl_xor_sync(0xffffffffu, s, o);
        if (lane == 0) red[ii][warp] = s;
    }
    __syncthreads();
    if (tid < 4)
        scal[tid] = 1.f / (red[tid][0] + red[tid][1] + red[tid][2] + red[tid][3]);
    __syncthreads();

    for (int j = tid; j < n; j += 128) {
#pragma unroll
        for (int ii = 0; ii < 4; ii++)
            Atgn[((size_t)bt * n + i0 + ii) * n + j] =
                kGA * (adj[(size_t)(i0 + ii) * n + j] + rowbuf[ii][j] * scal[ii]);
    }
}

__global__ void k_pack_tgn(const float* __restrict__ X, float* __restrict__ chainT, int n)
{
    int i = blockIdx.x * blockDim.x + threadIdx.x;
    int total = cB4 * n * cF;
    if (i >= total) return;
    int f = i % cF;
    int row = i / cF;
    int nn = row % n, bt = row / n;
    int b = bt >> 2, t = bt & 3;
    chainT[(size_t)row * 6 + f] =
        X[((((size_t)b * cT) + (cT - 4) + t) * n + nn) * cF + f];
}

// fused tgn matmul + relu + sum over t
__global__ void k_tgn_out(const float* __restrict__ chainT,
                          const float* __restrict__ tw, const float* __restrict__ tb,
                          float* __restrict__ tar2, int n)
{
    int gid = blockIdx.x * blockDim.x + threadIdx.x;
    int total = cB * n * cTGN;
    if (gid >= total) return;
    int m = gid & (cTGN - 1);
    int row = gid / cTGN;
    int nn = row % n, b = row / n;
    float tot = 0.f;
#pragma unroll
    for (int t = 0; t < 4; t++) {
        const float* cr = chainT + (((size_t)(b * 4 + t) * n) + nn) * 6;
        float s = tb[m];
#pragma unroll
        for (int k = 0; k < 6; k++)
            s = fmaf(cr[k], tw[k * cTGN + m], s);
        tot += fmaxf(s, 0.f);
    }
    tar2[gid] = tot;
}

// generic small FC: in1 (sliced) [+ in2 dense-ish]; mode 0 plain, 1 transposed store
__global__ void k_fc(const float* __restrict__ in1, int ld1, int sw1, int C1, int ns1,
                     const float* __restrict__ in2, int ld2, int C2,
                     const float* __restrict__ W, const float* __restrict__ Bv, int M,
                     float* __restrict__ out, int mode, int n, int rows)
{
    int gid = blockIdx.x * blockDim.x + threadIdx.x;
    if (gid >= rows * M) return;
    int m = gid % M;
    int row = gid / M;
    float acc = Bv[m];
    int k = 0;
    const float* r1 = in1 + (size_t)row * ld1;
    for (int s = 0; s < ns1; s++)
        for (int c = 0; c < C1; c++)
            acc = fmaf(r1[s * sw1 + c], W[(k++) * M + m], acc);
    if (in2) {
        const float* r2 = in2 + (size_t)row * ld2;
        for (int c = 0; c < C2; c++)
            acc = fmaf(r2[c], W[(k++) * M + m], acc);
    }
    if (mode == 0) out[(size_t)row * M + m] = acc;
    else {
        int nn = row % n, b = row / n;
        out[((size_t)b * M + m) * n + nn] = acc;
    }
}

// ---------------- host orchestration ----------------

struct Ptrs {
    float *chainS, *chainZ, *chainC, *coef, *ns, *nt, *z;
    float *Atgn, *q, *k, *chainT, *tar2, *gat;
};

// One GRU step. Assumes chainZ/chainC slice0 are already packed for this step.
// If nextCur != null, packs the next step's inputs inside k_gcu.
static void gru_step(const float* cur, size_t curBs, const float* adj,
                     const float* a1w, const float* a1b, const float* a2w, const float* a2b,
                     const float* sw, const float* sb, const float* tw, const float* tb,
                     const float* zw, const float* zb, const float* rw, const float* rb,
                     const float* cw, const float* cb,
                     const float* nextCur, size_t nextBs, const Ptrs& P)
{
    const int n = cN;
    dim3 gg(DIV_UP(n, 32), cB);

    k_gconv2<<<gg, 192>>>(P.chainS, cH, 0, 1, adj, 0, kGA, n);
    k_gconv2<<<gg, 192>>>(P.chainS, cH, 1, 2, adj, 0, kGA, n);

    k_agg<<<DIV_UP(cB * n * cHYP, 256), 256>>>(cur, curBs, P.chainS,
        a1w, a1b, a2w, a2b, sw, sb, tw, tb, P.ns, P.nt, n);

    k_adpcoef<<<dim3(n / 4, cB), 128>>>(P.ns, P.nt, adj, P.coef, n);

    k_gconv2<<<gg, 192>>>(P.chainZ, cF + cH, 0, 1, P.coef, (size_t)n * n, 1.f, n);
    k_gconv2<<<gg, 192>>>(P.chainZ, cF + cH, 1, 2, P.coef, (size_t)n * n, 1.f, n);

    k_gate2<<<DIV_UP(cB * n * cH, 256), 256>>>(P.chainZ, P.chainS, P.chainC,
        zw, zb, rw, rb, P.z, n);

    k_gconv2<<<gg, 192>>>(P.chainC, cF + cH, 0, 1, P.coef, (size_t)n * n, 1.f, n);
    k_gconv2<<<gg, 192>>>(P.chainC, cF + cH, 1, 2, P.coef, (size_t)n * n, 1.f, n);

    k_gcu<<<DIV_UP(cB * n * cH, 256), 256>>>(P.chainC, P.chainS, P.z, cw, cb,
        nextCur, nextBs, P.chainZ, P.chainC, n);
}

extern "C" void kernel_launch(void* const* d_in, const int* in_sizes, int n_in,
                              void* d_out, int out_size)
{
    const float* X      = (const float*)d_in[0];
    const float* adj    = (const float*)d_in[1];
    const float* wq_w   = (const float*)d_in[7];
    const float* wq_b   = (const float*)d_in[8];
    const float* wk_w   = (const float*)d_in[9];
    const float* wk_b   = (const float*)d_in[10];
    const float* trans_w= (const float*)d_in[11];
    const float* tgn_w  = (const float*)d_in[12];
    const float* tgn_b  = (const float*)d_in[13];
    const float* agg1_w = (const float*)d_in[14];
    const float* agg1_b = (const float*)d_in[15];
    const float* agg2_w = (const float*)d_in[16];
    const float* agg2_b = (const float*)d_in[17];
    const float* src_w  = (const float*)d_in[18];
    const float* src_b  = (const float*)d_in[19];
    const float* tgt_w  = (const float*)d_in[20];
    const float* tgt_b  = (const float*)d_in[21];
    const float* gz_w   = (const float*)d_in[22];
    const float* gz_b   = (const float*)d_in[23];
    const float* gr_w   = (const float*)d_in[24];
    const float* gr_b   = (const float*)d_in[25];
    const float* gc_w   = (const float*)d_in[26];
    const float* gc_b   = (const float*)d_in[27];
    const float* fcs_w  = (const float*)d_in[28];
    const float* fcs_b  = (const float*)d_in[29];
    const float* fcm_w  = (const float*)d_in[30];
    const float* fcm_b  = (const float*)d_in[31];
    float* out = (float*)d_out;

    Ptrs P;
    cudaGetSymbolAddress((void**)&P.chainS, g_chainS);
    cudaGetSymbolAddress((void**)&P.chainZ, g_chainZ);
    cudaGetSymbolAddress((void**)&P.chainC, g_chainC);
    cudaGetSymbolAddress((void**)&P.coef,   g_coef);
    cudaGetSymbolAddress((void**)&P.ns,     g_ns);
    cudaGetSymbolAddress((void**)&P.nt,     g_nt);
    cudaGetSymbolAddress((void**)&P.z,      g_z);
    cudaGetSymbolAddress((void**)&P.Atgn,   g_Atgn);
    cudaGetSymbolAddress((void**)&P.q,      g_q);
    cudaGetSymbolAddress((void**)&P.k,      g_k);
    cudaGetSymbolAddress((void**)&P.chainT, g_chainT);
    cudaGetSymbolAddress((void**)&P.tar2,   g_tar2);
    cudaGetSymbolAddress((void**)&P.gat,    g_gat);

    const size_t Xbs = (size_t)cT * cN * cF;

    // hidden (chainS) = 0 — deterministic per call
    k_zero<<<DIV_UP(cB * cN * LDCH, 256), 256>>>(P.chainS, cB * cN * LDCH);

    // pack for step 0 (hidden = 0)
    k_pack<<<DIV_UP(cB * cN * CP, 256), 256>>>(X, Xbs, P.chainS, P.chainZ, P.chainC, cN);

    // warmup GRU steps: t = 0,4,8,12,16 (each packs the next one's inputs, except the last)
    for (int t = 0; t + 4 < cT; t += 4) {
        const float* nextCur = (t + 8 < cT) ? (X + (size_t)(t + 4) * cN * cF) : nullptr;
        gru_step(X + (size_t)t * cN * cF, Xbs, adj,
                 agg1_w, agg1_b, agg2_w, agg2_b, src_w, src_b, tgt_w, tgt_b,
                 gz_w, gz_b, gr_w, gr_b, gc_w, gc_b,
                 nextCur, Xbs, P);
    }

    // attention block
    k_qk<<<DIV_UP(cB4 * cN * cD, 256), 256>>>(X, wq_w, wq_b, wk_w, wk_b, P.q, P.k, cN);
    k_attn<<<dim3(cN / 4, cB4), 128>>>(P.q, P.k, trans_w, adj, P.Atgn, cN);

    // TGN gcn (C=2) with A_tgn
    k_pack_tgn<<<DIV_UP(cB4 * cN * cF, 256), 256>>>(X, P.chainT, cN);
    dim3 ggt(DIV_UP(cN, 128), cB4);
    k_gconv_f2<<<ggt, 128>>>(P.chainT, 0, 1, P.Atgn, cN);
    k_gconv_f2<<<ggt, 128>>>(P.chainT, 1, 2, P.Atgn, cN);
    k_tgn_out<<<DIV_UP(cB * cN * cTGN, 256), 256>>>(P.chainT, tgn_w, tgn_b, P.tar2, cN);

    // gat = tar2 @ fcs
    k_fc<<<DIV_UP(cB * cN * cF, 256), 256>>>(P.tar2, cTGN, 0, cTGN, 1,
        nullptr, 0, 0, fcs_w, fcs_b, cF, P.gat, 0, cN, cB * cN);

    // pack + final GRU step
    k_pack<<<DIV_UP(cB * cN * CP, 256), 256>>>(P.gat, (size_t)cN * cF, P.chainS,
        P.chainZ, P.chainC, cN);
    gru_step(P.gat, (size_t)cN * cF, adj,
             agg1_w, agg1_b, agg2_w, agg2_b, src_w, src_b, tgt_w, tgt_b,
             gz_w, gz_b, gr_w, gr_b, gc_w, gc_b,
             nullptr, 0, P);

    // out[b, l, n] = concat([tar2, hidden]) @ fcm_w + fcm_b (transposed store)
    k_fc<<<DIV_UP(cB * cN * cLEN, 256), 256>>>(P.tar2, cTGN, 0, cTGN, 1,
        P.chainS, LDCH, cH, fcm_w, fcm_b, cLEN, out, 1, cN, cB * cN);
}

// round 5
// speedup vs baseline: 2.7766x; 1.1802x over previous
#include <cuda_runtime.h>
#include <cstdint>
#include <math.h>

#define DIV_UP(a,b) (((a)+(b)-1)/(b))

// Problem constants
constexpr int cB   = 16;
constexpr int cT   = 24;
constexpr int cN   = 500;
constexpr int cF   = 2;
constexpr int cH   = 64;
constexpr int cD   = 8;
constexpr int cTGN = 32;
constexpr int cHYP = 16;
constexpr int cLEN = 24;
constexpr int cB4  = cB * 4;

constexpr float kAL = 0.05f, kBE = 0.95f, kGA = 0.95f, kTAU = 2.0f;

// padded chain layout: 3 slices of 72 floats each, row stride 216
constexpr int CP   = 72;
constexpr int LDCH = 216;

// ---------------- scratch ----------------
__device__ float g_chainS[cB * cN * LDCH];   // slice0 = hidden (persistent per call)
__device__ float g_chainZ[cB * cN * LDCH];
__device__ float g_chainC[cB * cN * LDCH];
__device__ float g_coef[(size_t)cB * cN * cN];
__device__ float g_ns[cB * cN * cHYP];
__device__ float g_nt[cB * cN * cHYP];
__device__ float g_z[cB * cN * cH];
__device__ float g_Atgn[(size_t)cB4 * cN * cN];
__device__ float g_q[cB * cN * cD];
__device__ float g_k[cB4 * cN * cD];
__device__ float g_chainT[cB4 * cN * 6];
__device__ float g_tar2[cB * cN * cTGN];
__device__ float g_gat[cB * cN * cF];

__device__ __forceinline__ float tanh_fast(float x) {
    float y;
    asm("tanh.approx.f32 %0, %1;" : "=f"(y) : "f"(x));
    return y;
}
__device__ __forceinline__ float sigmoid_fast(float x) {
    return 1.f / (1.f + __expf(-x));
}
__device__ __forceinline__ void cp_async16(uint32_t saddr, const void* gptr, int psize) {
    asm volatile("cp.async.ca.shared.global [%0], [%1], 16, %2;\n"
                 :: "r"(saddr), "l"(gptr), "r"(psize));
}
__device__ __forceinline__ void cp_commit() {
    asm volatile("cp.async.commit_group;\n");
}
template <int N>
__device__ __forceinline__ void cp_wait() {
    asm volatile("cp.async.wait_group %0;\n" :: "n"(N));
}

// ---------------- kernels ----------------

__global__ void k_zero(float* p, int ntot) {
    int i = blockIdx.x * blockDim.x + threadIdx.x;
    if (i < ntot) p[i] = 0.f;
}

// Register-tiled graph conv, double-buffered cp.async mainloop.
// buf[:,w,sOut*CP+c] = AL*buf[:,w,c] + scale * sum_v A[b,v,w]*buf[:,v,sIn*CP+c]
// block 192 thr = 6 warps; warp cg owns channels [12*cg,12*cg+12); lane wi owns w=w0+wi
__global__ __launch_bounds__(192) void k_gconv2(
    float* __restrict__ buf, int C, int sIn, int sOut,
    const float* __restrict__ A, size_t Abs, float scale, int n)
{
    const int b  = blockIdx.y;
    const int w0 = blockIdx.x * 32;
    const int tid = threadIdx.x;
    const int wi = tid & 31;
    const int cg = tid >> 5;              // 0..5
    const int c0 = cg * 12;

    __shared__ float cf[2][32][36];       // [stage][v][w]
    __shared__ float hs[2][32][76];       // [stage][v][c]

    float acc[12];
#pragma unroll
    for (int j = 0; j < 12; j++) acc[j] = 0.f;

    const float* Ab = A + (size_t)b * Abs;
    const float* hb = buf + (size_t)b * n * LDCH + sIn * CP;

    const int ntiles = DIV_UP(n, 32);

    auto load_tile = [&](int t, int stage) {
        int v0 = t * 32;
#pragma unroll
        for (int it = 0; it < 2; it++) {
            int idx = tid + it * 192;
            if (idx < 256) {
                int vi = idx >> 3, seg = idx & 7;
                int v = v0 + vi, w = w0 + seg * 4;
                bool ok = (v < n) && (w < n);
                const float* src = Ab + (size_t)(ok ? v : 0) * n + (ok ? w : 0);
                uint32_t dst = (uint32_t)__cvta_generic_to_shared(&cf[stage][vi][seg * 4]);
                cp_async16(dst, src, ok ? 16 : 0);
            }
        }
#pragma unroll
        for (int it = 0; it < 3; it++) {
            int idx = tid + it * 192;
            int vi = idx / 18, seg = idx % 18;
            int v = v0 + vi;
            bool ok = (v < n);
            const float* src = hb + (size_t)(ok ? v : 0) * LDCH + seg * 4;
            uint32_t dst = (uint32_t)__cvta_generic_to_shared(&hs[stage][vi][seg * 4]);
            cp_async16(dst, src, ok ? 16 : 0);
        }
    };

    load_tile(0, 0);
    cp_commit();

    for (int t = 0; t < ntiles; t++) {
        int cur = t & 1;
        if (t + 1 < ntiles) {
            load_tile(t + 1, (t + 1) & 1);
            cp_commit();
            cp_wait<1>();
        } else {
            cp_wait<0>();
        }
        __syncthreads();

#pragma unroll
        for (int v = 0; v < 32; v++) {
            float cv = cf[cur][v][wi];
            float4 ha = *(float4*)&hs[cur][v][c0];
            float4 hm = *(float4*)&hs[cur][v][c0 + 4];
            float4 hc = *(float4*)&hs[cur][v][c0 + 8];
            acc[0]  = fmaf(cv, ha.x, acc[0]);
            acc[1]  = fmaf(cv, ha.y, acc[1]);
            acc[2]  = fmaf(cv, ha.z, acc[2]);
            acc[3]  = fmaf(cv, ha.w, acc[3]);
            acc[4]  = fmaf(cv, hm.x, acc[4]);
            acc[5]  = fmaf(cv, hm.y, acc[5]);
            acc[6]  = fmaf(cv, hm.z, acc[6]);
            acc[7]  = fmaf(cv, hm.w, acc[7]);
            acc[8]  = fmaf(cv, hc.x, acc[8]);
            acc[9]  = fmaf(cv, hc.y, acc[9]);
            acc[10] = fmaf(cv, hc.z, acc[10]);
            acc[11] = fmaf(cv, hc.w, acc[11]);
        }
        __syncthreads();
    }

    int w = w0 + wi;
    if (w < n) {
        float* op = buf + ((size_t)b * n + w) * LDCH;
#pragma unroll
        for (int j = 0; j < 12; j++) {
            int c = c0 + j;
            if (c < C) op[sOut * CP + c] = kAL * op[c] + scale * acc[j];
        }
    }
}

// C=2 graph conv for the TGN path (A already includes GA scaling)
__global__ __launch_bounds__(128) void k_gconv_f2(
    float* __restrict__ buf, int sIn, int sOut,
    const float* __restrict__ A, int n)
{
    int bt = blockIdx.y;
    int w0 = blockIdx.x * 128;
    int tid = threadIdx.x;
    __shared__ float As[2][32][132];
    __shared__ float2 xs[2][32];
    float a0 = 0.f, a1 = 0.f;
    const float* Ab = A + (size_t)bt * n * n;
    const float* hb = buf + (size_t)bt * n * 6 + sIn * 2;

    const int ntiles = DIV_UP(n, 32);

    auto load_tile = [&](int t, int stage) {
        int v0 = t * 32;
#pragma unroll
        for (int it = 0; it < 8; it++) {
            int idx = tid + it * 128;
            int vi = idx >> 5, seg = idx & 31;
            int v = v0 + vi, w = w0 + seg * 4;
            bool ok = (v < n) && (w < n);
            const float* src = Ab + (size_t)(ok ? v : 0) * n + (ok ? w : 0);
            uint32_t dst = (uint32_t)__cvta_generic_to_shared(&As[stage][vi][seg * 4]);
            cp_async16(dst, src, ok ? 16 : 0);
        }
        if (tid < 32) {
            int v = v0 + tid;
            bool ok = (v < n);
            const float* src = hb + (size_t)(ok ? v : 0) * 6;
            uint32_t dst = (uint32_t)__cvta_generic_to_shared(&xs[stage][tid]);
            asm volatile("cp.async.ca.shared.global [%0], [%1], 8, %2;\n"
                         :: "r"(dst), "l"(src), "r"(ok ? 8 : 0));
        }
    };

    load_tile(0, 0);
    cp_commit();

    for (int t = 0; t < ntiles; t++) {
        int cur = t & 1;
        if (t + 1 < ntiles) {
            load_tile(t + 1, (t + 1) & 1);
            cp_commit();
            cp_wait<1>();
        } else {
            cp_wait<0>();
        }
        __syncthreads();
#pragma unroll
        for (int v = 0; v < 32; v++) {
            float a = As[cur][v][tid];
            float2 x = xs[cur][v];
            a0 = fmaf(a, x.x, a0);
            a1 = fmaf(a, x.y, a1);
        }
        __syncthreads();
    }
    int w = w0 + tid;
    if (w < n) {
        float* op = buf + ((size_t)bt * n + w) * 6;
        op[sOut * 2]     = kAL * op[0] + a0;
        op[sOut * 2 + 1] = kAL * op[1] + a1;
    }
}

// pack step inputs: chainZ slice0 = [cur, hidden, 0pad]; chainC slice0 = [cur, 0..]
__global__ void k_pack(const float* __restrict__ cur, size_t curBs,
                       const float* __restrict__ chainS,
                       float* __restrict__ chainZ, float* __restrict__ chainC, int n)
{
    int i = blockIdx.x * blockDim.x + threadIdx.x;
    int total = cB * n * CP;
    if (i >= total) return;
    int c = i % CP;
    int row = i / CP;
    int nn = row % n, b = row / n;
    float vz = 0.f, vc = 0.f;
    if (c < cF) {
        float x = cur[(size_t)b * curBs + (size_t)nn * cF + c];
        vz = x; vc = x;
    } else if (c < cF + cH) {
        vz = chainS[(size_t)row * LDCH + (c - cF)];
    }
    chainZ[(size_t)row * LDCH + c] = vz;
    chainC[(size_t)row * LDCH + c] = vc;
}

// fused: gs, gt (K=192 over chainS), then ns, nt
__global__ void k_agg(const float* __restrict__ cur, size_t curBs,
                      const float* __restrict__ chainS,
                      const float* __restrict__ a1w, const float* __restrict__ a1b,
                      const float* __restrict__ a2w, const float* __restrict__ a2b,
                      const float* __restrict__ sw, const float* __restrict__ sb,
                      const float* __restrict__ tw, const float* __restrict__ tb,
                      float* __restrict__ ns, float* __restrict__ nt, int n)
{
    int gid = blockIdx.x * blockDim.x + threadIdx.x;
    int total = cB * n * cHYP;
    if (gid >= total) return;
    int j = gid & (cHYP - 1);
    int row = gid / cHYP;
    int nn = row % n, b = row / n;

    const float* ch = chainS + (size_t)row * LDCH;
    float g1 = a1b[j], g2 = a2b[j];
#pragma unroll
    for (int s = 0; s < 3; s++) {
        const float* cs = ch + s * CP;
        const float* w1 = a1w + (size_t)s * cH * cHYP + j;
        const float* w2 = a2w + (size_t)s * cH * cHYP + j;
#pragma unroll 8
        for (int c = 0; c < cH; c++) {
            float v = cs[c];
            g1 = fmaf(v, w1[c * cHYP], g1);
            g2 = fmaf(v, w2[c * cHYP], g2);
        }
    }
    const float* xr = cur + (size_t)b * curBs + (size_t)nn * cF;
    float x0 = xr[0], x1 = xr[1];
    float ps = sb[j] + x0 * sw[j] + x1 * sw[cHYP + j];
    float pt = tb[j] + x0 * tw[j] + x1 * tw[cHYP + j];
    ns[gid] = tanh_fast(kTAU * ps * g1);
    nt[gid] = tanh_fast(kTAU * pt * g2);
}

// adp rows (4 per block) folded into combined gconv coefficient: coef = BE*adp + GA*adj
__global__ __launch_bounds__(128) void k_adpcoef(
    const float* __restrict__ ns, const float* __restrict__ nt,
    const float* __restrict__ adj, float* __restrict__ coef, int n)
{
    int b = blockIdx.y, i0 = blockIdx.x * 4;
    int tid = threadIdx.x;
    int lane = tid & 31, warp = tid >> 5;

    __shared__ float nsr[4][16], ntr[4][16];
    __shared__ float rowbuf[4][512];
    __shared__ float red[4][4];
    __shared__ float invs[4];

    if (tid < 64) {
        int ii = tid >> 4, c = tid & 15;
        nsr[ii][c] = ns[((size_t)b * n + i0 + ii) * 16 + c];
    } else {
        int t = tid - 64;
        int ii = t >> 4, c = t & 15;
        ntr[ii][c] = nt[((size_t)b * n + i0 + ii) * 16 + c];
    }
    __syncthreads();

    float lsum[4] = {0.f, 0.f, 0.f, 0.f};
    for (int m = tid; m < n; m += 128) {
        const float4* nsm = (const float4*)(ns + ((size_t)b * n + m) * 16);
        const float4* ntm = (const float4*)(nt + ((size_t)b * n + m) * 16);
        float4 s0 = nsm[0], s1 = nsm[1], s2 = nsm[2], s3 = nsm[3];
        float4 t0 = ntm[0], t1 = ntm[1], t2 = ntm[2], t3 = ntm[3];
        float sm[16] = {s0.x,s0.y,s0.z,s0.w, s1.x,s1.y,s1.z,s1.w,
                        s2.x,s2.y,s2.z,s2.w, s3.x,s3.y,s3.z,s3.w};
        float tm[16] = {t0.x,t0.y,t0.z,t0.w, t1.x,t1.y,t1.z,t1.w,
                        t2.x,t2.y,t2.z,t2.w, t3.x,t3.y,t3.z,t3.w};
#pragma unroll
        for (int ii = 0; ii < 4; ii++) {
            float a = 0.f;
#pragma unroll
            for (int c = 0; c < 16; c++)
                a += nsr[ii][c] * tm[c] - ntr[ii][c] * sm[c];
            float v = fmaxf(tanh_fast(kTAU * a), 0.f);
            if (m == i0 + ii) v += 1.f;
            rowbuf[ii][m] = v;
            lsum[ii] += v;
        }
    }
#pragma unroll
    for (int ii = 0; ii < 4; ii++) {
        float s = lsum[ii];
#pragma unroll
        for (int o = 16; o > 0; o >>= 1) s += __shfl_xor_sync(0xffffffffu, s, o);
        if (lane == 0) red[ii][warp] = s;
    }
    __syncthreads();
    if (tid < 4)
        invs[tid] = kBE / (red[tid][0] + red[tid][1] + red[tid][2] + red[tid][3]);
    __syncthreads();

    for (int m = tid; m < n; m += 128) {
#pragma unroll
        for (int ii = 0; ii < 4; ii++)
            coef[((size_t)b * n + i0 + ii) * n + m] =
                rowbuf[ii][m] * invs[ii] + kGA * adj[(size_t)(i0 + ii) * n + m];
    }
}

// fused z & r gates; writes r*hidden into chainC slice0
__global__ void k_gate2(const float* __restrict__ chainZ, const float* __restrict__ chainS,
                        float* __restrict__ chainC,
                        const float* __restrict__ zw, const float* __restrict__ zbv,
                        const float* __restrict__ rw, const float* __restrict__ rbv,
                        float* __restrict__ zout, int n)
{
    int gid = blockIdx.x * blockDim.x + threadIdx.x;
    int total = cB * n * cH;
    if (gid >= total) return;
    int m = gid & (cH - 1);
    int row = gid >> 6;

    const float* ch = chainZ + (size_t)row * LDCH;
    float az = zbv[m], ar = rbv[m];
#pragma unroll
    for (int s = 0; s < 3; s++) {
        const float* cs = ch + s * CP;
        const float* wz = zw + (size_t)s * 66 * cH + m;
        const float* wr = rw + (size_t)s * 66 * cH + m;
#pragma unroll 6
        for (int c = 0; c < 66; c++) {
            float v = cs[c];
            az = fmaf(v, wz[c * cH], az);
            ar = fmaf(v, wr[c * cH], ar);
        }
    }
    float z = sigmoid_fast(az);
    float r = sigmoid_fast(ar);
    zout[gid] = z;
    chainC[(size_t)row * LDCH + cF + m] = r * chainS[(size_t)row * LDCH + m];
}

// fused c-gate + GRU hidden update; optionally packs next step inputs
__global__ void k_gcu(const float* __restrict__ chainC, float* __restrict__ chainS,
                      const float* __restrict__ zbuf,
                      const float* __restrict__ cw, const float* __restrict__ cbv,
                      const float* __restrict__ nextCur, size_t nextBs,
                      float* __restrict__ chainZ, float* __restrict__ chainCp, int n)
{
    int gid = blockIdx.x * blockDim.x + threadIdx.x;
    int total = cB * n * cH;
    if (gid >= total) return;
    int m = gid & (cH - 1);
    int row = gid >> 6;

    const float* ch = chainC + (size_t)row * LDCH;
    float ac = cbv[m];
#pragma unroll
    for (int s = 0; s < 3; s++) {
        const float* cs = ch + s * CP;
        const float* wc = cw + (size_t)s * 66 * cH + m;
#pragma unroll 6
        for (int c = 0; c < 66; c++)
            ac = fmaf(cs[c], wc[c * cH], ac);
    }
    float cval = tanh_fast(ac);
    float z = zbuf[gid];
    float* hp = chainS + (size_t)row * LDCH + m;
    float hnew = z * (*hp) + (1.f - z) * cval;
    *hp = hnew;
    if (nextCur) {
        chainZ[(size_t)row * LDCH + cF + m] = hnew;
        if (m < cF) {
            int nn = row % n, b = row / n;
            float x = nextCur[(size_t)b * nextBs + (size_t)nn * cF + m];
            chainZ[(size_t)row * LDCH + m]  = x;
            chainCp[(size_t)row * LDCH + m] = x;
        }
    }
}

// q/k projections for attention
__global__ void k_qk(const float* __restrict__ X,
                     const float* __restrict__ wqw, const float* __restrict__ wqb,
                     const float* __restrict__ wkw, const float* __restrict__ wkb,
                     float* __restrict__ q, float* __restrict__ kk, int n)
{
    int i = blockIdx.x * blockDim.x + threadIdx.x;
    int total = cB4 * n * cD;
    if (i >= total) return;
    int d = i % cD;
    int row = i / cD;
    int nn = row % n, bt = row / n;
    int b = bt >> 2, t = bt & 3;
    const float* xr = X + ((((size_t)b * cT) + (cT - 4) + t) * n + nn) * cF;
    kk[i] = wkb[d] + xr[0] * wkw[d] + xr[1] * wkw[cD + d];
    if (t == 3)
        q[((size_t)b * n + nn) * cD + d] = wqb[d] + xr[0] * wqw[d] + xr[1] * wqw[cD + d];
}

// scores + softmax + A_tgn = GA*(adj + attn); 4 rows i per block
__global__ __launch_bounds__(128) void k_attn(
    const float* __restrict__ q, const float* __restrict__ kk,
    const float* __restrict__ tw, const float* __restrict__ adj,
    float* __restrict__ Atgn, int n)
{
    int bt = blockIdx.y, i0 = blockIdx.x * 4;
    int b = bt >> 2;
    int tid = threadIdx.x;
    int lane = tid & 31, warp = tid >> 5;

    __shared__ float qd[4][8], twv[8];
    __shared__ float rowbuf[4][512];
    __shared__ float red[4][4];
    __shared__ float scal[4];

    if (tid < 32) {
        int ii = tid >> 3, d = tid & 7;
        qd[ii][d] = q[((size_t)b * n + i0 + ii) * 8 + d];
    } else if (tid < 40) {
        twv[tid - 32] = tw[tid - 32];
    }
    __syncthreads();

    float lmax[4] = {-1e30f, -1e30f, -1e30f, -1e30f};
    for (int j = tid; j < n; j += 128) {
        const float4* kj4 = (const float4*)(kk + ((size_t)bt * n + j) * 8);
        float4 k0 = kj4[0], k1 = kj4[1];
        float kj[8] = {k0.x,k0.y,k0.z,k0.w, k1.x,k1.y,k1.z,k1.w};
#pragma unroll
        for (int ii = 0; ii < 4; ii++) {
            float s = 0.f;
#pragma unroll
            for (int d = 0; d < 8; d++)
                s = fmaf(tanh_fast(qd[ii][d] + kj[d]), twv[d], s);
            rowbuf[ii][j] = s;
            lmax[ii] = fmaxf(lmax[ii], s);
        }
    }
#pragma unroll
    for (int ii = 0; ii < 4; ii++) {
        float s = lmax[ii];
#pragma unroll
        for (int o = 16; o > 0; o >>= 1) s = fmaxf(s, __shfl_xor_sync(0xffffffffu, s, o));
        if (lane == 0) red[ii][warp] = s;
    }
    __syncthreads();
    if (tid < 4)
        scal[tid] = fmaxf(fmaxf(red[tid][0], red[tid][1]), fmaxf(red[tid][2], red[tid][3]));
    __syncthreads();

    float lsum[4] = {0.f, 0.f, 0.f, 0.f};
    for (int j = tid; j < n; j += 128) {
#pragma unroll
        for (int ii = 0; ii < 4; ii++) {
            float e = __expf(rowbuf[ii][j] - scal[ii]);
            rowbuf[ii][j] = e;
            lsum[ii] += e;
        }
    }
#pragma unroll
    for (int ii = 0; ii < 4; ii++) {
        float s = lsum[ii];
#pragma unroll
        for (int o = 16; o > 0; o >>= 1) s += __shfl_xor_sync(0xffffffffu, s, o);
        if (lane == 0) red[ii][warp] = s;
    }
    __syncthreads();
    if (tid < 4)
        scal[tid] = 1.f / (red[tid][0] + red[tid][1] + red[tid][2] + red[tid][3]);
    __syncthreads();

    for (int j = tid; j < n; j += 128) {
#pragma unroll
        for (int ii = 0; ii < 4; ii++)
            Atgn[((size_t)bt * n + i0 + ii) * n + j] =
                kGA * (adj[(size_t)(i0 + ii) * n + j] + rowbuf[ii][j] * scal[ii]);
    }
}

__global__ void k_pack_tgn(const float* __restrict__ X, float* __restrict__ chainT, int n)
{
    int i = blockIdx.x * blockDim.x + threadIdx.x;
    int total = cB4 * n * cF;
    if (i >= total) return;
    int f = i % cF;
    int row = i / cF;
    int nn = row % n, bt = row / n;
    int b = bt >> 2, t = bt & 3;
    chainT[(size_t)row * 6 + f] =
        X[((((size_t)b * cT) + (cT - 4) + t) * n + nn) * cF + f];
}

// fused tgn matmul + relu + sum over t
__global__ void k_tgn_out(const float* __restrict__ chainT,
                          const float* __restrict__ tw, const float* __restrict__ tb,
                          float* __restrict__ tar2, int n)
{
    int gid = blockIdx.x * blockDim.x + threadIdx.x;
    int total = cB * n * cTGN;
    if (gid >= total) return;
    int m = gid & (cTGN - 1);
    int row = gid / cTGN;
    int nn = row % n, b = row / n;
    float tot = 0.f;
#pragma unroll
    for (int t = 0; t < 4; t++) {
        const float* cr = chainT + (((size_t)(b * 4 + t) * n) + nn) * 6;
        float s = tb[m];
#pragma unroll
        for (int k = 0; k < 6; k++)
            s = fmaf(cr[k], tw[k * cTGN + m], s);
        tot += fmaxf(s, 0.f);
    }
    tar2[gid] = tot;
}

// generic small FC: in1 (sliced) [+ in2 dense-ish]; mode 0 plain, 1 transposed store
__global__ void k_fc(const float* __restrict__ in1, int ld1, int sw1, int C1, int ns1,
                     const float* __restrict__ in2, int ld2, int C2,
                     const float* __restrict__ W, const float* __restrict__ Bv, int M,
                     float* __restrict__ out, int mode, int n, int rows)
{
    int gid = blockIdx.x * blockDim.x + threadIdx.x;
    if (gid >= rows * M) return;
    int m = gid % M;
    int row = gid / M;
    float acc = Bv[m];
    int k = 0;
    const float* r1 = in1 + (size_t)row * ld1;
    for (int s = 0; s < ns1; s++)
        for (int c = 0; c < C1; c++)
            acc = fmaf(r1[s * sw1 + c], W[(k++) * M + m], acc);
    if (in2) {
        const float* r2 = in2 + (size_t)row * ld2;
        for (int c = 0; c < C2; c++)
            acc = fmaf(r2[c], W[(k++) * M + m], acc);
    }
    if (mode == 0) out[(size_t)row * M + m] = acc;
    else {
        int nn = row % n, b = row / n;
        out[((size_t)b * M + m) * n + nn] = acc;
    }
}

// ---------------- host orchestration ----------------

struct Ptrs {
    float *chainS, *chainZ, *chainC, *coef, *ns, *nt, *z;
    float *Atgn, *q, *k, *chainT, *tar2, *gat;
};

// One GRU step. Assumes chainZ/chainC slice0 are already packed for this step.
// If nextCur != null, packs the next step's inputs inside k_gcu.
static void gru_step(const float* cur, size_t curBs, const float* adj,
                     const float* a1w, const float* a1b, const float* a2w, const float* a2b,
                     const float* sw, const float* sb, const float* tw, const float* tb,
                     const float* zw, const float* zb, const float* rw, const float* rb,
                     const float* cw, const float* cb,
                     const float* nextCur, size_t nextBs, const Ptrs& P)
{
    const int n = cN;
    dim3 gg(DIV_UP(n, 32), cB);

    k_gconv2<<<gg, 192>>>(P.chainS, cH, 0, 1, adj, 0, kGA, n);
    k_gconv2<<<gg, 192>>>(P.chainS, cH, 1, 2, adj, 0, kGA, n);

    k_agg<<<DIV_UP(cB * n * cHYP, 256), 256>>>(cur, curBs, P.chainS,
        a1w, a1b, a2w, a2b, sw, sb, tw, tb, P.ns, P.nt, n);

    k_adpcoef<<<dim3(n / 4, cB), 128>>>(P.ns, P.nt, adj, P.coef, n);

    k_gconv2<<<gg, 192>>>(P.chainZ, cF + cH, 0, 1, P.coef, (size_t)n * n, 1.f, n);
    k_gconv2<<<gg, 192>>>(P.chainZ, cF + cH, 1, 2, P.coef, (size_t)n * n, 1.f, n);

    k_gate2<<<DIV_UP(cB * n * cH, 256), 256>>>(P.chainZ, P.chainS, P.chainC,
        zw, zb, rw, rb, P.z, n);

    k_gconv2<<<gg, 192>>>(P.chainC, cF + cH, 0, 1, P.coef, (size_t)n * n, 1.f, n);
    k_gconv2<<<gg, 192>>>(P.chainC, cF + cH, 1, 2, P.coef, (size_t)n * n, 1.f, n);

    k_gcu<<<DIV_UP(cB * n * cH, 256), 256>>>(P.chainC, P.chainS, P.z, cw, cb,
        nextCur, nextBs, P.chainZ, P.chainC, n);
}

extern "C" void kernel_launch(void* const* d_in, const int* in_sizes, int n_in,
                              void* d_out, int out_size)
{
    const float* X      = (const float*)d_in[0];
    const float* adj    = (const float*)d_in[1];
    const float* wq_w   = (const float*)d_in[7];
    const float* wq_b   = (const float*)d_in[8];
    const float* wk_w   = (const float*)d_in[9];
    const float* wk_b   = (const float*)d_in[10];
    const float* trans_w= (const float*)d_in[11];
    const float* tgn_w  = (const float*)d_in[12];
    const float* tgn_b  = (const float*)d_in[13];
    const float* agg1_w = (const float*)d_in[14];
    const float* agg1_b = (const float*)d_in[15];
    const float* agg2_w = (const float*)d_in[16];
    const float* agg2_b = (const float*)d_in[17];
    const float* src_w  = (const float*)d_in[18];
    const float* src_b  = (const float*)d_in[19];
    const float* tgt_w  = (const float*)d_in[20];
    const float* tgt_b  = (const float*)d_in[21];
    const float* gz_w   = (const float*)d_in[22];
    const float* gz_b   = (const float*)d_in[23];
    const float* gr_w   = (const float*)d_in[24];
    const float* gr_b   = (const float*)d_in[25];
    const float* gc_w   = (const float*)d_in[26];
    const float* gc_b   = (const float*)d_in[27];
    const float* fcs_w  = (const float*)d_in[28];
    const float* fcs_b  = (const float*)d_in[29];
    const float* fcm_w  = (const float*)d_in[30];
    const float* fcm_b  = (const float*)d_in[31];
    float* out = (float*)d_out;

    Ptrs P;
    cudaGetSymbolAddress((void**)&P.chainS, g_chainS);
    cudaGetSymbolAddress((void**)&P.chainZ, g_chainZ);
    cudaGetSymbolAddress((void**)&P.chainC, g_chainC);
    cudaGetSymbolAddress((void**)&P.coef,   g_coef);
    cudaGetSymbolAddress((void**)&P.ns,     g_ns);
    cudaGetSymbolAddress((void**)&P.nt,     g_nt);
    cudaGetSymbolAddress((void**)&P.z,      g_z);
    cudaGetSymbolAddress((void**)&P.Atgn,   g_Atgn);
    cudaGetSymbolAddress((void**)&P.q,      g_q);
    cudaGetSymbolAddress((void**)&P.k,      g_k);
    cudaGetSymbolAddress((void**)&P.chainT, g_chainT);
    cudaGetSymbolAddress((void**)&P.tar2,   g_tar2);
    cudaGetSymbolAddress((void**)&P.gat,    g_gat);

    const size_t Xbs = (size_t)cT * cN * cF;

    // hidden (chainS) = 0 — deterministic per call
    k_zero<<<DIV_UP(cB * cN * LDCH, 256), 256>>>(P.chainS, cB * cN * LDCH);

    // pack for step 0 (hidden = 0)
    k_pack<<<DIV_UP(cB * cN * CP, 256), 256>>>(X, Xbs, P.chainS, P.chainZ, P.chainC, cN);

    // warmup GRU steps: t = 0,4,8,12,16 (each packs the next one's inputs, except the last)
    for (int t = 0; t + 4 < cT; t += 4) {
        const float* nextCur = (t + 8 < cT) ? (X + (size_t)(t + 4) * cN * cF) : nullptr;
        gru_step(X + (size_t)t * cN * cF, Xbs, adj,
                 agg1_w, agg1_b, agg2_w, agg2_b, src_w, src_b, tgt_w, tgt_b,
                 gz_w, gz_b, gr_w, gr_b, gc_w, gc_b,
                 nextCur, Xbs, P);
    }

    // attention block
    k_qk<<<DIV_UP(cB4 * cN * cD, 256), 256>>>(X, wq_w, wq_b, wk_w, wk_b, P.q, P.k, cN);
    k_attn<<<dim3(cN / 4, cB4), 128>>>(P.q, P.k, trans_w, adj, P.Atgn, cN);

    // TGN gcn (C=2) with A_tgn
    k_pack_tgn<<<DIV_UP(cB4 * cN * cF, 256), 256>>>(X, P.chainT, cN);
    dim3 ggt(DIV_UP(cN, 128), cB4);
    k_gconv_f2<<<ggt, 128>>>(P.chainT, 0, 1, P.Atgn, cN);
    k_gconv_f2<<<ggt, 128>>>(P.chainT, 1, 2, P.Atgn, cN);
    k_tgn_out<<<DIV_UP(cB * cN * cTGN, 256), 256>>>(P.chainT, tgn_w, tgn_b, P.tar2, cN);

    // gat = tar2 @ fcs
    k_fc<<<DIV_UP(cB * cN * cF, 256), 256>>>(P.tar2, cTGN, 0, cTGN, 1,
        nullptr, 0, 0, fcs_w, fcs_b, cF, P.gat, 0, cN, cB * cN);

    // pack + final GRU step
    k_pack<<<DIV_UP(cB * cN * CP, 256), 256>>>(P.gat, (size_t)cN * cF, P.chainS,
        P.chainZ, P.chainC, cN);
    gru_step(P.gat, (size_t)cN * cF, adj,
             agg1_w, agg1_b, agg2_w, agg2_b, src_w, src_b, tgt_w, tgt_b,
             gz_w, gz_b, gr_w, gr_b, gc_w, gc_b,
             nullptr, 0, P);

    // out[b, l, n] = concat([tar2, hidden]) @ fcm_w + fcm_b (transposed store)
    k_fc<<<DIV_UP(cB * cN * cLEN, 256), 256>>>(P.tar2, cTGN, 0, cTGN, 1,
        P.chainS, LDCH, cH, fcm_w, fcm_b, cLEN, out, 1, cN, cB * cN);
}

// round 6
// speedup vs baseline: 3.3847x; 1.2190x over previous
#include <cuda_runtime.h>
#include <cstdint>
#include <math.h>

#define DIV_UP(a,b) (((a)+(b)-1)/(b))

// Problem constants
constexpr int cB   = 16;
constexpr int cT   = 24;
constexpr int cN   = 500;
constexpr int cF   = 2;
constexpr int cH   = 64;
constexpr int cD   = 8;
constexpr int cTGN = 32;
constexpr int cHYP = 16;
constexpr int cLEN = 24;
constexpr int cB4  = cB * 4;

constexpr float kAL = 0.05f, kBE = 0.95f, kGA = 0.95f, kTAU = 2.0f;

// padded chain layout: 3 slices of 72 floats each, row stride 216
constexpr int CP   = 72;
constexpr int LDCH = 216;

// ---------------- scratch ----------------
__device__ float g_chainS[cB * cN * LDCH];   // slice0 = hidden (persistent per call)
__device__ float g_chainZ[cB * cN * LDCH];
__device__ float g_chainC[cB * cN * LDCH];
__device__ float g_coef[(size_t)cB * cN * cN];
__device__ float g_ns[cB * cN * cHYP];
__device__ float g_nt[cB * cN * cHYP];
__device__ float g_z[cB * cN * cH];
__device__ float g_Atgn[(size_t)cB4 * cN * cN];
__device__ float g_q[cB * cN * cD];
__device__ float g_k[cB4 * cN * cD];
__device__ float g_chainT[cB4 * cN * 6];
__device__ float g_tar2[cB * cN * cTGN];
__device__ float g_gat[cB * cN * cF];

__device__ __forceinline__ float tanh_fast(float x) {
    float y;
    asm("tanh.approx.f32 %0, %1;" : "=f"(y) : "f"(x));
    return y;
}
__device__ __forceinline__ float sigmoid_fast(float x) {
    return 1.f / (1.f + __expf(-x));
}
__device__ __forceinline__ void cp_async16(uint32_t saddr, const void* gptr, int psize) {
    asm volatile("cp.async.ca.shared.global [%0], [%1], 16, %2;\n"
                 :: "r"(saddr), "l"(gptr), "r"(psize));
}
__device__ __forceinline__ void cp_commit() {
    asm volatile("cp.async.commit_group;\n");
}
template <int N>
__device__ __forceinline__ void cp_wait() {
    asm volatile("cp.async.wait_group %0;\n" :: "n"(N));
}
__device__ __forceinline__ uint32_t f2tf(float x) {
    uint32_t r;
    asm("cvt.rna.tf32.f32 %0, %1;" : "=r"(r) : "f"(x));
    return r;
}
__device__ __forceinline__ void mma_tf32(float* c,
    uint32_t a0, uint32_t a1, uint32_t a2, uint32_t a3,
    uint32_t b0, uint32_t b1)
{
    asm volatile(
        "mma.sync.aligned.m16n8k8.row.col.f32.tf32.tf32.f32 "
        "{%0,%1,%2,%3}, {%4,%5,%6,%7}, {%8,%9}, {%0,%1,%2,%3};"
        : "+f"(c[0]), "+f"(c[1]), "+f"(c[2]), "+f"(c[3])
        : "r"(a0), "r"(a1), "r"(a2), "r"(a3), "r"(b0), "r"(b1));
}

// ---------------- kernels ----------------

__global__ void k_zero(float* p, int ntot) {
    int i = blockIdx.x * blockDim.x + threadIdx.x;
    if (i < ntot) p[i] = 0.f;
}

// Tensor-core graph conv (3xTF32 compensated), double-buffered cp.async mainloop.
// out[w, sOut*CP+c] = AL*buf[w,c] + scale * sum_v A[b,v,w] * buf[v, sIn*CP+c]
// GEMM view: D[w,c] (M=32/block) = A'[w,v] (=cf[v][w]) * B[v,c] (=hs[v][c])
// block 192 thr = 6 warps: warp grid 2(w) x 3(c); warp tile m16 x n24, K-chunk 32.
__global__ __launch_bounds__(192) void k_gconv2(
    float* __restrict__ buf, int C, int sIn, int sOut,
    const float* __restrict__ A, size_t Abs, float scale, int n)
{
    const int b  = blockIdx.y;
    const int w0 = blockIdx.x * 32;
    const int tid = threadIdx.x;
    const int lane = tid & 31;
    const int warp = tid >> 5;            // 0..5
    const int wb = (warp & 1) * 16;       // warp w offset in tile
    const int cb = (warp >> 1) * 24;      // warp c offset in tile
    const int lq = lane >> 2;             // 0..7
    const int lr = lane & 3;              // 0..3

    __shared__ float cf[2][32][36];       // [stage][v][w]
    __shared__ float hs[2][32][76];       // [stage][v][c]

    float acc[3][4];
#pragma unroll
    for (int i = 0; i < 3; i++)
#pragma unroll
        for (int j = 0; j < 4; j++) acc[i][j] = 0.f;

    const float* Ab = A + (size_t)b * Abs;
    const float* hb = buf + (size_t)b * n * LDCH + sIn * CP;

    const int ntiles = DIV_UP(n, 32);

    auto load_tile = [&](int t, int stage) {
        int v0 = t * 32;
#pragma unroll
        for (int it = 0; it < 2; it++) {
            int idx = tid + it * 192;
            if (idx < 256) {
                int vi = idx >> 3, seg = idx & 7;
                int v = v0 + vi, w = w0 + seg * 4;
                bool ok = (v < n) && (w < n);
                const float* src = Ab + (size_t)(ok ? v : 0) * n + (ok ? w : 0);
                uint32_t dst = (uint32_t)__cvta_generic_to_shared(&cf[stage][vi][seg * 4]);
                cp_async16(dst, src, ok ? 16 : 0);
            }
        }
#pragma unroll
        for (int it = 0; it < 3; it++) {
            int idx = tid + it * 192;
            int vi = idx / 18, seg = idx % 18;
            int v = v0 + vi;
            bool ok = (v < n);
            const float* src = hb + (size_t)(ok ? v : 0) * LDCH + seg * 4;
            uint32_t dst = (uint32_t)__cvta_generic_to_shared(&hs[stage][vi][seg * 4]);
            cp_async16(dst, src, ok ? 16 : 0);
        }
    };

    load_tile(0, 0);
    cp_commit();

    for (int t = 0; t < ntiles; t++) {
        int cur = t & 1;
        if (t + 1 < ntiles) {
            load_tile(t + 1, (t + 1) & 1);
            cp_commit();
            cp_wait<1>();
        } else {
            cp_wait<0>();
        }
        __syncthreads();

        const float (*cfc)[36] = cf[cur];
        const float (*hsc)[76] = hs[cur];

#pragma unroll
        for (int k8 = 0; k8 < 4; k8++) {
            int kb = k8 * 8;
            // A fragment (m16k8, row-major): A[m=w][k=v] = cf[v][w]
            float ar0 = cfc[kb + lr][wb + lq];
            float ar1 = cfc[kb + lr][wb + lq + 8];
            float ar2 = cfc[kb + lr + 4][wb + lq];
            float ar3 = cfc[kb + lr + 4][wb + lq + 8];
            uint32_t ah0 = f2tf(ar0), ah1 = f2tf(ar1), ah2 = f2tf(ar2), ah3 = f2tf(ar3);
            uint32_t al0 = f2tf(ar0 - __uint_as_float(ah0));
            uint32_t al1 = f2tf(ar1 - __uint_as_float(ah1));
            uint32_t al2 = f2tf(ar2 - __uint_as_float(ah2));
            uint32_t al3 = f2tf(ar3 - __uint_as_float(ah3));

#pragma unroll
            for (int ct = 0; ct < 3; ct++) {
                // B fragment (k8n8, col-major): B[k=v][n=c] = hs[v][c]
                float br0 = hsc[kb + lr][cb + ct * 8 + lq];
                float br1 = hsc[kb + lr + 4][cb + ct * 8 + lq];
                uint32_t bh0 = f2tf(br0), bh1 = f2tf(br1);
                uint32_t bl0 = f2tf(br0 - __uint_as_float(bh0));
                uint32_t bl1 = f2tf(br1 - __uint_as_float(bh1));

                mma_tf32(acc[ct], ah0, ah1, ah2, ah3, bh0, bh1);
                mma_tf32(acc[ct], al0, al1, al2, al3, bh0, bh1);
                mma_tf32(acc[ct], ah0, ah1, ah2, ah3, bl0, bl1);
            }
        }
        __syncthreads();
    }

    // epilogue: D fragment rows (w) = w0+wb+lq (+8), cols (c) = cb+ct*8+lr*2 (+1)
    int wr0 = w0 + wb + lq;
    int wr1 = wr0 + 8;
#pragma unroll
    for (int ct = 0; ct < 3; ct++) {
        int c = cb + ct * 8 + lr * 2;
        if (wr0 < n) {
            float* op = buf + ((size_t)b * n + wr0) * LDCH;
            if (c < C)     op[sOut * CP + c]     = kAL * op[c]     + scale * acc[ct][0];
            if (c + 1 < C) op[sOut * CP + c + 1] = kAL * op[c + 1] + scale * acc[ct][1];
        }
        if (wr1 < n) {
            float* op = buf + ((size_t)b * n + wr1) * LDCH;
            if (c < C)     op[sOut * CP + c]     = kAL * op[c]     + scale * acc[ct][2];
            if (c + 1 < C) op[sOut * CP + c + 1] = kAL * op[c + 1] + scale * acc[ct][3];
        }
    }
}

// C=2 graph conv for the TGN path (A already includes GA scaling)
__global__ __launch_bounds__(128) void k_gconv_f2(
    float* __restrict__ buf, int sIn, int sOut,
    const float* __restrict__ A, int n)
{
    int bt = blockIdx.y;
    int w0 = blockIdx.x * 128;
    int tid = threadIdx.x;
    __shared__ float As[2][32][132];
    __shared__ float2 xs[2][32];
    float a0 = 0.f, a1 = 0.f;
    const float* Ab = A + (size_t)bt * n * n;
    const float* hb = buf + (size_t)bt * n * 6 + sIn * 2;

    const int ntiles = DIV_UP(n, 32);

    auto load_tile = [&](int t, int stage) {
        int v0 = t * 32;
#pragma unroll
        for (int it = 0; it < 8; it++) {
            int idx = tid + it * 128;
            int vi = idx >> 5, seg = idx & 31;
            int v = v0 + vi, w = w0 + seg * 4;
            bool ok = (v < n) && (w < n);
            const float* src = Ab + (size_t)(ok ? v : 0) * n + (ok ? w : 0);
            uint32_t dst = (uint32_t)__cvta_generic_to_shared(&As[stage][vi][seg * 4]);
            cp_async16(dst, src, ok ? 16 : 0);
        }
        if (tid < 32) {
            int v = v0 + tid;
            bool ok = (v < n);
            const float* src = hb + (size_t)(ok ? v : 0) * 6;
            uint32_t dst = (uint32_t)__cvta_generic_to_shared(&xs[stage][tid]);
            asm volatile("cp.async.ca.shared.global [%0], [%1], 8, %2;\n"
                         :: "r"(dst), "l"(src), "r"(ok ? 8 : 0));
        }
    };

    load_tile(0, 0);
    cp_commit();

    for (int t = 0; t < ntiles; t++) {
        int cur = t & 1;
        if (t + 1 < ntiles) {
            load_tile(t + 1, (t + 1) & 1);
            cp_commit();
            cp_wait<1>();
        } else {
            cp_wait<0>();
        }
        __syncthreads();
#pragma unroll
        for (int v = 0; v < 32; v++) {
            float a = As[cur][v][tid];
            float2 x = xs[cur][v];
            a0 = fmaf(a, x.x, a0);
            a1 = fmaf(a, x.y, a1);
        }
        __syncthreads();
    }
    int w = w0 + tid;
    if (w < n) {
        float* op = buf + ((size_t)bt * n + w) * 6;
        op[sOut * 2]     = kAL * op[0] + a0;
        op[sOut * 2 + 1] = kAL * op[1] + a1;
    }
}

// pack step inputs: chainZ slice0 = [cur, hidden, 0pad]; chainC slice0 = [cur, 0..]
__global__ void k_pack(const float* __restrict__ cur, size_t curBs,
                       const float* __restrict__ chainS,
                       float* __restrict__ chainZ, float* __restrict__ chainC, int n)
{
    int i = blockIdx.x * blockDim.x + threadIdx.x;
    int total = cB * n * CP;
    if (i >= total) return;
    int c = i % CP;
    int row = i / CP;
    int nn = row % n, b = row / n;
    float vz = 0.f, vc = 0.f;
    if (c < cF) {
        float x = cur[(size_t)b * curBs + (size_t)nn * cF + c];
        vz = x; vc = x;
    } else if (c < cF + cH) {
        vz = chainS[(size_t)row * LDCH + (c - cF)];
    }
    chainZ[(size_t)row * LDCH + c] = vz;
    chainC[(size_t)row * LDCH + c] = vc;
}

// fused: gs, gt (K=192 over chainS), then ns, nt
__global__ void k_agg(const float* __restrict__ cur, size_t curBs,
                      const float* __restrict__ chainS,
                      const float* __restrict__ a1w, const float* __restrict__ a1b,
                      const float* __restrict__ a2w, const float* __restrict__ a2b,
                      const float* __restrict__ sw, const float* __restrict__ sb,
                      const float* __restrict__ tw, const float* __restrict__ tb,
                      float* __restrict__ ns, float* __restrict__ nt, int n)
{
    int gid = blockIdx.x * blockDim.x + threadIdx.x;
    int total = cB * n * cHYP;
    if (gid >= total) return;
    int j = gid & (cHYP - 1);
    int row = gid / cHYP;
    int nn = row % n, b = row / n;

    const float* ch = chainS + (size_t)row * LDCH;
    float g1 = a1b[j], g2 = a2b[j];
#pragma unroll
    for (int s = 0; s < 3; s++) {
        const float* cs = ch + s * CP;
        const float* w1 = a1w + (size_t)s * cH * cHYP + j;
        const float* w2 = a2w + (size_t)s * cH * cHYP + j;
#pragma unroll 8
        for (int c = 0; c < cH; c++) {
            float v = cs[c];
            g1 = fmaf(v, w1[c * cHYP], g1);
            g2 = fmaf(v, w2[c * cHYP], g2);
        }
    }
    const float* xr = cur + (size_t)b * curBs + (size_t)nn * cF;
    float x0 = xr[0], x1 = xr[1];
    float ps = sb[j] + x0 * sw[j] + x1 * sw[cHYP + j];
    float pt = tb[j] + x0 * tw[j] + x1 * tw[cHYP + j];
    ns[gid] = tanh_fast(kTAU * ps * g1);
    nt[gid] = tanh_fast(kTAU * pt * g2);
}

// adp rows (4 per block) folded into combined gconv coefficient: coef = BE*adp + GA*adj
__global__ __launch_bounds__(128) void k_adpcoef(
    const float* __restrict__ ns, const float* __restrict__ nt,
    const float* __restrict__ adj, float* __restrict__ coef, int n)
{
    int b = blockIdx.y, i0 = blockIdx.x * 4;
    int tid = threadIdx.x;
    int lane = tid & 31, warp = tid >> 5;

    __shared__ float nsr[4][16], ntr[4][16];
    __shared__ float rowbuf[4][512];
    __shared__ float red[4][4];
    __shared__ float invs[4];

    if (tid < 64) {
        int ii = tid >> 4, c = tid & 15;
        nsr[ii][c] = ns[((size_t)b * n + i0 + ii) * 16 + c];
    } else {
        int t = tid - 64;
        int ii = t >> 4, c = t & 15;
        ntr[ii][c] = nt[((size_t)b * n + i0 + ii) * 16 + c];
    }
    __syncthreads();

    float lsum[4] = {0.f, 0.f, 0.f, 0.f};
    for (int m = tid; m < n; m += 128) {
        const float4* nsm = (const float4*)(ns + ((size_t)b * n + m) * 16);
        const float4* ntm = (const float4*)(nt + ((size_t)b * n + m) * 16);
        float4 s0 = nsm[0], s1 = nsm[1], s2 = nsm[2], s3 = nsm[3];
        float4 t0 = ntm[0], t1 = ntm[1], t2 = ntm[2], t3 = ntm[3];
        float sm[16] = {s0.x,s0.y,s0.z,s0.w, s1.x,s1.y,s1.z,s1.w,
                        s2.x,s2.y,s2.z,s2.w, s3.x,s3.y,s3.z,s3.w};
        float tm[16] = {t0.x,t0.y,t0.z,t0.w, t1.x,t1.y,t1.z,t1.w,
                        t2.x,t2.y,t2.z,t2.w, t3.x,t3.y,t3.z,t3.w};
#pragma unroll
        for (int ii = 0; ii < 4; ii++) {
            float a = 0.f;
#pragma unroll
            for (int c = 0; c < 16; c++)
                a += nsr[ii][c] * tm[c] - ntr[ii][c] * sm[c];
            float v = fmaxf(tanh_fast(kTAU * a), 0.f);
            if (m == i0 + ii) v += 1.f;
            rowbuf[ii][m] = v;
            lsum[ii] += v;
        }
    }
#pragma unroll
    for (int ii = 0; ii < 4; ii++) {
        float s = lsum[ii];
#pragma unroll
        for (int o = 16; o > 0; o >>= 1) s += __shfl_xor_sync(0xffffffffu, s, o);
        if (lane == 0) red[ii][warp] = s;
    }
    __syncthreads();
    if (tid < 4)
        invs[tid] = kBE / (red[tid][0] + red[tid][1] + red[tid][2] + red[tid][3]);
    __syncthreads();

    for (int m = tid; m < n; m += 128) {
#pragma unroll
        for (int ii = 0; ii < 4; ii++)
            coef[((size_t)b * n + i0 + ii) * n + m] =
                rowbuf[ii][m] * invs[ii] + kGA * adj[(size_t)(i0 + ii) * n + m];
    }
}

// fused z & r gates; writes r*hidden into chainC slice0
__global__ void k_gate2(const float* __restrict__ chainZ, const float* __restrict__ chainS,
                        float* __restrict__ chainC,
                        const float* __restrict__ zw, const float* __restrict__ zbv,
                        const float* __restrict__ rw, const float* __restrict__ rbv,
                        float* __restrict__ zout, int n)
{
    int gid = blockIdx.x * blockDim.x + threadIdx.x;
    int total = cB * n * cH;
    if (gid >= total) return;
    int m = gid & (cH - 1);
    int row = gid >> 6;

    const float* ch = chainZ + (size_t)row * LDCH;
    float az = zbv[m], ar = rbv[m];
#pragma unroll
    for (int s = 0; s < 3; s++) {
        const float* cs = ch + s * CP;
        const float* wz = zw + (size_t)s * 66 * cH + m;
        const float* wr = rw + (size_t)s * 66 * cH + m;
#pragma unroll 6
        for (int c = 0; c < 66; c++) {
            float v = cs[c];
            az = fmaf(v, wz[c * cH], az);
            ar = fmaf(v, wr[c * cH], ar);
        }
    }
    float z = sigmoid_fast(az);
    float r = sigmoid_fast(ar);
    zout[gid] = z;
    chainC[(size_t)row * LDCH + cF + m] = r * chainS[(size_t)row * LDCH + m];
}

// fused c-gate + GRU hidden update; optionally packs next step inputs
__global__ void k_gcu(const float* __restrict__ chainC, float* __restrict__ chainS,
                      const float* __restrict__ zbuf,
                      const float* __restrict__ cw, const float* __restrict__ cbv,
                      const float* __restrict__ nextCur, size_t nextBs,
                      float* __restrict__ chainZ, float* __restrict__ chainCp, int n)
{
    int gid = blockIdx.x * blockDim.x + threadIdx.x;
    int total = cB * n * cH;
    if (gid >= total) return;
    int m = gid & (cH - 1);
    int row = gid >> 6;

    const float* ch = chainC + (size_t)row * LDCH;
    float ac = cbv[m];
#pragma unroll
    for (int s = 0; s < 3; s++) {
        const float* cs = ch + s * CP;
        const float* wc = cw + (size_t)s * 66 * cH + m;
#pragma unroll 6
        for (int c = 0; c < 66; c++)
            ac = fmaf(cs[c], wc[c * cH], ac);
    }
    float cval = tanh_fast(ac);
    float z = zbuf[gid];
    float* hp = chainS + (size_t)row * LDCH + m;
    float hnew = z * (*hp) + (1.f - z) * cval;
    *hp = hnew;
    if (nextCur) {
        chainZ[(size_t)row * LDCH + cF + m] = hnew;
        if (m < cF) {
            int nn = row % n, b = row / n;
            float x = nextCur[(size_t)b * nextBs + (size_t)nn * cF + m];
            chainZ[(size_t)row * LDCH + m]  = x;
            chainCp[(size_t)row * LDCH + m] = x;
        }
    }
}

// q/k projections for attention
__global__ void k_qk(const float* __restrict__ X,
                     const float* __restrict__ wqw, const float* __restrict__ wqb,
                     const float* __restrict__ wkw, const float* __restrict__ wkb,
                     float* __restrict__ q, float* __restrict__ kk, int n)
{
    int i = blockIdx.x * blockDim.x + threadIdx.x;
    int total = cB4 * n * cD;
    if (i >= total) return;
    int d = i % cD;
    int row = i / cD;
    int nn = row % n, bt = row / n;
    int b = bt >> 2, t = bt & 3;
    const float* xr = X + ((((size_t)b * cT) + (cT - 4) + t) * n + nn) * cF;
    kk[i] = wkb[d] + xr[0] * wkw[d] + xr[1] * wkw[cD + d];
    if (t == 3)
        q[((size_t)b * n + nn) * cD + d] = wqb[d] + xr[0] * wqw[d] + xr[1] * wqw[cD + d];
}

// scores + softmax + A_tgn = GA*(adj + attn); 4 rows i per block
__global__ __launch_bounds__(128) void k_attn(
    const float* __restrict__ q, const float* __restrict__ kk,
    const float* __restrict__ tw, const float* __restrict__ adj,
    float* __restrict__ Atgn, int n)
{
    int bt = blockIdx.y, i0 = blockIdx.x * 4;
    int b = bt >> 2;
    int tid = threadIdx.x;
    int lane = tid & 31, warp = tid >> 5;

    __shared__ float qd[4][8], twv[8];
    __shared__ float rowbuf[4][512];
    __shared__ float red[4][4];
    __shared__ float scal[4];

    if (tid < 32) {
        int ii = tid >> 3, d = tid & 7;
        qd[ii][d] = q[((size_t)b * n + i0 + ii) * 8 + d];
    } else if (tid < 40) {
        twv[tid - 32] = tw[tid - 32];
    }
    __syncthreads();

    float lmax[4] = {-1e30f, -1e30f, -1e30f, -1e30f};
    for (int j = tid; j < n; j += 128) {
        const float4* kj4 = (const float4*)(kk + ((size_t)bt * n + j) * 8);
        float4 k0 = kj4[0], k1 = kj4[1];
        float kj[8] = {k0.x,k0.y,k0.z,k0.w, k1.x,k1.y,k1.z,k1.w};
#pragma unroll
        for (int ii = 0; ii < 4; ii++) {
            float s = 0.f;
#pragma unroll
            for (int d = 0; d < 8; d++)
                s = fmaf(tanh_fast(qd[ii][d] + kj[d]), twv[d], s);
            rowbuf[ii][j] = s;
            lmax[ii] = fmaxf(lmax[ii], s);
        }
    }
#pragma unroll
    for (int ii = 0; ii < 4; ii++) {
        float s = lmax[ii];
#pragma unroll
        for (int o = 16; o > 0; o >>= 1) s = fmaxf(s, __shfl_xor_sync(0xffffffffu, s, o));
        if (lane == 0) red[ii][warp] = s;
    }
    __syncthreads();
    if (tid < 4)
        scal[tid] = fmaxf(fmaxf(red[tid][0], red[tid][1]), fmaxf(red[tid][2], red[tid][3]));
    __syncthreads();

    float lsum[4] = {0.f, 0.f, 0.f, 0.f};
    for (int j = tid; j < n; j += 128) {
#pragma unroll
        for (int ii = 0; ii < 4; ii++) {
            float e = __expf(rowbuf[ii][j] - scal[ii]);
            rowbuf[ii][j] = e;
            lsum[ii] += e;
        }
    }
#pragma unroll
    for (int ii = 0; ii < 4; ii++) {
        float s = lsum[ii];
#pragma unroll
        for (int o = 16; o > 0; o >>= 1) s += __shfl_xor_sync(0xffffffffu, s, o);
        if (lane == 0) red[ii][warp] = s;
    }
    __syncthreads();
    if (tid < 4)
        scal[tid] = 1.f / (red[tid][0] + red[tid][1] + red[tid][2] + red[tid][3]);
    __syncthreads();

    for (int j = tid; j < n; j += 128) {
#pragma unroll
        for (int ii = 0; ii < 4; ii++)
            Atgn[((size_t)bt * n + i0 + ii) * n + j] =
                kGA * (adj[(size_t)(i0 + ii) * n + j] + rowbuf[ii][j] * scal[ii]);
    }
}

__global__ void k_pack_tgn(const float* __restrict__ X, float* __restrict__ chainT, int n)
{
    int i = blockIdx.x * blockDim.x + threadIdx.x;
    int total = cB4 * n * cF;
    if (i >= total) return;
    int f = i % cF;
    int row = i / cF;
    int nn = row % n, bt = row / n;
    int b = bt >> 2, t = bt & 3;
    chainT[(size_t)row * 6 + f] =
        X[((((size_t)b * cT) + (cT - 4) + t) * n + nn) * cF + f];
}

// fused tgn matmul + relu + sum over t
__global__ void k_tgn_out(const float* __restrict__ chainT,
                          const float* __restrict__ tw, const float* __restrict__ tb,
                          float* __restrict__ tar2, int n)
{
    int gid = blockIdx.x * blockDim.x + threadIdx.x;
    int total = cB * n * cTGN;
    if (gid >= total) return;
    int m = gid & (cTGN - 1);
    int row = gid / cTGN;
    int nn = row % n, b = row / n;
    float tot = 0.f;
#pragma unroll
    for (int t = 0; t < 4; t++) {
        const float* cr = chainT + (((size_t)(b * 4 + t) * n) + nn) * 6;
        float s = tb[m];
#pragma unroll
        for (int k = 0; k < 6; k++)
            s = fmaf(cr[k], tw[k * cTGN + m], s);
        tot += fmaxf(s, 0.f);
    }
    tar2[gid] = tot;
}

// generic small FC: in1 (sliced) [+ in2 dense-ish]; mode 0 plain, 1 transposed store
__global__ void k_fc(const float* __restrict__ in1, int ld1, int sw1, int C1, int ns1,
                     const float* __restrict__ in2, int ld2, int C2,
                     const float* __restrict__ W, const float* __restrict__ Bv, int M,
                     float* __restrict__ out, int mode, int n, int rows)
{
    int gid = blockIdx.x * blockDim.x + threadIdx.x;
    if (gid >= rows * M) return;
    int m = gid % M;
    int row = gid / M;
    float acc = Bv[m];
    int k = 0;
    const float* r1 = in1 + (size_t)row * ld1;
    for (int s = 0; s < ns1; s++)
        for (int c = 0; c < C1; c++)
            acc = fmaf(r1[s * sw1 + c], W[(k++) * M + m], acc);
    if (in2) {
        const float* r2 = in2 + (size_t)row * ld2;
        for (int c = 0; c < C2; c++)
            acc = fmaf(r2[c], W[(k++) * M + m], acc);
    }
    if (mode == 0) out[(size_t)row * M + m] = acc;
    else {
        int nn = row % n, b = row / n;
        out[((size_t)b * M + m) * n + nn] = acc;
    }
}

// ---------------- host orchestration ----------------

struct Ptrs {
    float *chainS, *chainZ, *chainC, *coef, *ns, *nt, *z;
    float *Atgn, *q, *k, *chainT, *tar2, *gat;
};

// One GRU step. Assumes chainZ/chainC slice0 are already packed for this step.
// If nextCur != null, packs the next step's inputs inside k_gcu.
static void gru_step(const float* cur, size_t curBs, const float* adj,
                     const float* a1w, const float* a1b, const float* a2w, const float* a2b,
                     const float* sw, const float* sb, const float* tw, const float* tb,
                     const float* zw, const float* zb, const float* rw, const float* rb,
                     const float* cw, const float* cb,
                     const float* nextCur, size_t nextBs, const Ptrs& P)
{
    const int n = cN;
    dim3 gg(DIV_UP(n, 32), cB);

    k_gconv2<<<gg, 192>>>(P.chainS, cH, 0, 1, adj, 0, kGA, n);
    k_gconv2<<<gg, 192>>>(P.chainS, cH, 1, 2, adj, 0, kGA, n);

    k_agg<<<DIV_UP(cB * n * cHYP, 256), 256>>>(cur, curBs, P.chainS,
        a1w, a1b, a2w, a2b, sw, sb, tw, tb, P.ns, P.nt, n);

    k_adpcoef<<<dim3(n / 4, cB), 128>>>(P.ns, P.nt, adj, P.coef, n);

    k_gconv2<<<gg, 192>>>(P.chainZ, cF + cH, 0, 1, P.coef, (size_t)n * n, 1.f, n);
    k_gconv2<<<gg, 192>>>(P.chainZ, cF + cH, 1, 2, P.coef, (size_t)n * n, 1.f, n);

    k_gate2<<<DIV_UP(cB * n * cH, 256), 256>>>(P.chainZ, P.chainS, P.chainC,
        zw, zb, rw, rb, P.z, n);

    k_gconv2<<<gg, 192>>>(P.chainC, cF + cH, 0, 1, P.coef, (size_t)n * n, 1.f, n);
    k_gconv2<<<gg, 192>>>(P.chainC, cF + cH, 1, 2, P.coef, (size_t)n * n, 1.f, n);

    k_gcu<<<DIV_UP(cB * n * cH, 256), 256>>>(P.chainC, P.chainS, P.z, cw, cb,
        nextCur, nextBs, P.chainZ, P.chainC, n);
}

extern "C" void kernel_launch(void* const* d_in, const int* in_sizes, int n_in,
                              void* d_out, int out_size)
{
    const float* X      = (const float*)d_in[0];
    const float* adj    = (const float*)d_in[1];
    const float* wq_w   = (const float*)d_in[7];
    const float* wq_b   = (const float*)d_in[8];
    const float* wk_w   = (const float*)d_in[9];
    const float* wk_b   = (const float*)d_in[10];
    const float* trans_w= (const float*)d_in[11];
    const float* tgn_w  = (const float*)d_in[12];
    const float* tgn_b  = (const float*)d_in[13];
    const float* agg1_w = (const float*)d_in[14];
    const float* agg1_b = (const float*)d_in[15];
    const float* agg2_w = (const float*)d_in[16];
    const float* agg2_b = (const float*)d_in[17];
    const float* src_w  = (const float*)d_in[18];
    const float* src_b  = (const float*)d_in[19];
    const float* tgt_w  = (const float*)d_in[20];
    const float* tgt_b  = (const float*)d_in[21];
    const float* gz_w   = (const float*)d_in[22];
    const float* gz_b   = (const float*)d_in[23];
    const float* gr_w   = (const float*)d_in[24];
    const float* gr_b   = (const float*)d_in[25];
    const float* gc_w   = (const float*)d_in[26];
    const float* gc_b   = (const float*)d_in[27];
    const float* fcs_w  = (const float*)d_in[28];
    const float* fcs_b  = (const float*)d_in[29];
    const float* fcm_w  = (const float*)d_in[30];
    const float* fcm_b  = (const float*)d_in[31];
    float* out = (float*)d_out;

    Ptrs P;
    cudaGetSymbolAddress((void**)&P.chainS, g_chainS);
    cudaGetSymbolAddress((void**)&P.chainZ, g_chainZ);
    cudaGetSymbolAddress((void**)&P.chainC, g_chainC);
    cudaGetSymbolAddress((void**)&P.coef,   g_coef);
    cudaGetSymbolAddress((void**)&P.ns,     g_ns);
    cudaGetSymbolAddress((void**)&P.nt,     g_nt);
    cudaGetSymbolAddress((void**)&P.z,      g_z);
    cudaGetSymbolAddress((void**)&P.Atgn,   g_Atgn);
    cudaGetSymbolAddress((void**)&P.q,      g_q);
    cudaGetSymbolAddress((void**)&P.k,      g_k);
    cudaGetSymbolAddress((void**)&P.chainT, g_chainT);
    cudaGetSymbolAddress((void**)&P.tar2,   g_tar2);
    cudaGetSymbolAddress((void**)&P.gat,    g_gat);

    const size_t Xbs = (size_t)cT * cN * cF;

    // hidden (chainS) = 0 — deterministic per call
    k_zero<<<DIV_UP(cB * cN * LDCH, 256), 256>>>(P.chainS, cB * cN * LDCH);

    // pack for step 0 (hidden = 0)
    k_pack<<<DIV_UP(cB * cN * CP, 256), 256>>>(X, Xbs, P.chainS, P.chainZ, P.chainC, cN);

    // warmup GRU steps: t = 0,4,8,12,16 (each packs the next one's inputs, except the last)
    for (int t = 0; t + 4 < cT; t += 4) {
        const float* nextCur = (t + 8 < cT) ? (X + (size_t)(t + 4) * cN * cF) : nullptr;
        gru_step(X + (size_t)t * cN * cF, Xbs, adj,
                 agg1_w, agg1_b, agg2_w, agg2_b, src_w, src_b, tgt_w, tgt_b,
                 gz_w, gz_b, gr_w, gr_b, gc_w, gc_b,
                 nextCur, Xbs, P);
    }

    // attention block
    k_qk<<<DIV_UP(cB4 * cN * cD, 256), 256>>>(X, wq_w, wq_b, wk_w, wk_b, P.q, P.k, cN);
    k_attn<<<dim3(cN / 4, cB4), 128>>>(P.q, P.k, trans_w, adj, P.Atgn, cN);

    // TGN gcn (C=2) with A_tgn
    k_pack_tgn<<<DIV_UP(cB4 * cN * cF, 256), 256>>>(X, P.chainT, cN);
    dim3 ggt(DIV_UP(cN, 128), cB4);
    k_gconv_f2<<<ggt, 128>>>(P.chainT, 0, 1, P.Atgn, cN);
    k_gconv_f2<<<ggt, 128>>>(P.chainT, 1, 2, P.Atgn, cN);
    k_tgn_out<<<DIV_UP(cB * cN * cTGN, 256), 256>>>(P.chainT, tgn_w, tgn_b, P.tar2, cN);

    // gat = tar2 @ fcs
    k_fc<<<DIV_UP(cB * cN * cF, 256), 256>>>(P.tar2, cTGN, 0, cTGN, 1,
        nullptr, 0, 0, fcs_w, fcs_b, cF, P.gat, 0, cN, cB * cN);

    // pack + final GRU step
    k_pack<<<DIV_UP(cB * cN * CP, 256), 256>>>(P.gat, (size_t)cN * cF, P.chainS,
        P.chainZ, P.chainC, cN);
    gru_step(P.gat, (size_t)cN * cF, adj,
             agg1_w, agg1_b, agg2_w, agg2_b, src_w, src_b, tgt_w, tgt_b,
             gz_w, gz_b, gr_w, gr_b, gc_w, gc_b,
             nullptr, 0, P);

    // out[b, l, n] = concat([tar2, hidden]) @ fcm_w + fcm_b (transposed store)
    k_fc<<<DIV_UP(cB * cN * cLEN, 256), 256>>>(P.tar2, cTGN, 0, cTGN, 1,
        P.chainS, LDCH, cH, fcm_w, fcm_b, cLEN, out, 1, cN, cB * cN);
}